// round 1
// baseline (speedup 1.0000x reference)
#include <cuda_runtime.h>
#include <math.h>

// Problem constants
#define D        256
#define N_NODES  4000
#define LL       3     // layers
#define VV       2     // views

// Gathered-row scratch layout:
//  Q region  : rows [0, 8640)  -- per type t: base_t + (xy*6 + vl)*S_t + s
//              content = proj(E[t, x, y, idx_t[vl*S+s]])
//  Pneg region: rows [8640, 10800) -- per type t: pbase_t + (o*6 + vl)*K_t + k
//              content = proj(E[others(t)[o], v, l, nidx_t[v,l,o,k]])
#define Q_ROWS     8640
#define PNEG_ROWS  2160
#define TOTAL_ROWS 10800

#define TM            64
#define PITCH         260          // smem row pitch (floats): 16B-aligned rows, broadcast reads
#define KC            32
#define PROJ_THREADS  128
#define PROJ_BLOCKS   169          // ceil(10800/64)

__device__ float g_proj[(size_t)PROJ_BLOCKS * TM * D];   // 11.1 MB scratch
__device__ float g_W1T[D * D];
__device__ float g_W2T[D * D];

// ---------------------------------------------------------------------------
__global__ void zero_out_kernel(float* out) { out[0] = 0.0f; }

// Transpose both weight matrices: WT[k][j] = W[j][k]
__global__ void transpose_kernel(const float* __restrict__ W1,
                                 const float* __restrict__ W2)
{
    int i = blockIdx.x * blockDim.x + threadIdx.x;   // 0 .. 131071
    int half = i >> 16;
    int r = i & 65535;
    int k = r >> 8, j = r & 255;
    if (half == 0) g_W1T[(k << 8) + j] = W1[(j << 8) + k];
    else           g_W2T[(k << 8) + j] = W2[(j << 8) + k];
}

// ---------------------------------------------------------------------------
// Map a global gathered-row id -> source embedding row pointer
__device__ __forceinline__ const float* map_src_row(
    int r, const float* __restrict__ E,
    const int* __restrict__ idxp, const int* __restrict__ idxr,
    const int* __restrict__ negp, const int* __restrict__ negr)
{
    if (r < Q_ROWS) {
        int t, local, S;
        if (r < 3600)      { t = 0; local = r;        S = 100; }
        else if (r < 7200) { t = 1; local = r - 3600; S = 100; }
        else if (r < 7920) { t = 2; local = r - 7200; S = 20;  }
        else               { t = 3; local = r - 7920; S = 20;  }
        int perxy = 6 * S;
        int xy  = local / perxy;
        int rem = local - xy * perxy;          // flattened (v*L+l)*S + s
        int node = (t < 2) ? idxp[t * 600 + rem] : idxr[(t - 2) * 120 + rem];
        int x = xy / LL, y = xy - x * LL;
        return E + ((size_t)(((t * VV + x) * LL + y) * N_NODES + node)) * D;
    } else {
        int rr = r - Q_ROWS;
        int t, local, K;
        if (rr < 900)       { t = 0; local = rr;        K = 50; }
        else if (rr < 1800) { t = 1; local = rr - 900;  K = 50; }
        else if (rr < 1980) { t = 2; local = rr - 1800; K = 10; }
        else                { t = 3; local = rr - 1980; K = 10; }
        int perO = 6 * K;
        int o   = local / perO;
        int vlk = local - o * perO;
        int vl  = vlk / K;
        int k   = vlk - vl * K;
        int off = (vl * 3 + o) * K + k;        // nidx layout [V,L,3,K]
        int node = (t < 2) ? negp[t * 900 + off] : negr[(t - 2) * 180 + off];
        int ot = o + (o >= t ? 1 : 0);         // others(t)[o]
        int v = vl / LL, l = vl - v * LL;
        return E + ((size_t)(((ot * VV + v) * LL + l) * N_NODES + node)) * D;
    }
}

// ---------------------------------------------------------------------------
// Gather + 2-layer MLP (relu) + L2 normalize. One block per 64 rows.
// Thread micro-tile: 8 rows x 16 cols (cols = u*64 + jg*4 + jj).
__global__ void __launch_bounds__(PROJ_THREADS)
proj_kernel(const float* __restrict__ E,
            const float* __restrict__ b1, const float* __restrict__ b2,
            const int* __restrict__ idxp, const int* __restrict__ idxr,
            const int* __restrict__ negp, const int* __restrict__ negr)
{
    extern __shared__ float sm[];
    float* buf = sm;                          // [TM][PITCH] : X, later reused as H
    float* Wc  = sm + TM * PITCH;             // [KC][D]
    const float** srcp = (const float**)(Wc + KC * D);   // 64 pointers

    const int tid = threadIdx.x;
    const int jg  = tid & 15;
    const int mg  = tid >> 4;
    const int r0  = blockIdx.x * TM;

    if (tid < TM) {
        int r = r0 + tid;
        srcp[tid] = (r < TOTAL_ROWS)
                  ? map_src_row(r, E, idxp, idxr, negp, negr)
                  : (const float*)0;
    }
    __syncthreads();

    // Load gathered X tile (row-major, pitch PITCH)
    for (int idx = tid; idx < TM * 64; idx += PROJ_THREADS) {
        int m = idx >> 6, q = idx & 63;
        const float* s = srcp[m];
        float4 v = make_float4(0.f, 0.f, 0.f, 0.f);
        if (s) v = ((const float4*)s)[q];
        *(float4*)(buf + m * PITCH + 4 * q) = v;
    }

    float acc[8][16];

    // ================= layer 1: H = relu(X @ W1^T + b1) =================
    #pragma unroll
    for (int mm = 0; mm < 8; mm++)
        #pragma unroll
        for (int jj = 0; jj < 16; jj++) acc[mm][jj] = 0.f;

    for (int kc = 0; kc < D; kc += KC) {
        __syncthreads();
        for (int idx = tid; idx < (KC * D) / 4; idx += PROJ_THREADS)
            ((float4*)Wc)[idx] = ((const float4*)(g_W1T + kc * D))[idx];
        __syncthreads();
        #pragma unroll 2
        for (int k = 0; k < KC; k++) {
            float a[8];
            #pragma unroll
            for (int mm = 0; mm < 8; mm++)
                a[mm] = buf[(mg * 8 + mm) * PITCH + kc + k];
            #pragma unroll
            for (int u = 0; u < 4; u++) {
                float4 b4 = *(const float4*)(Wc + k * D + u * 64 + jg * 4);
                #pragma unroll
                for (int mm = 0; mm < 8; mm++) {
                    acc[mm][u*4+0] = fmaf(a[mm], b4.x, acc[mm][u*4+0]);
                    acc[mm][u*4+1] = fmaf(a[mm], b4.y, acc[mm][u*4+1]);
                    acc[mm][u*4+2] = fmaf(a[mm], b4.z, acc[mm][u*4+2]);
                    acc[mm][u*4+3] = fmaf(a[mm], b4.w, acc[mm][u*4+3]);
                }
            }
        }
    }
    __syncthreads();   // all X reads done -> safe to overwrite buf with H

    // epilogue 1: bias + relu, write H into buf
    #pragma unroll
    for (int u = 0; u < 4; u++) {
        float4 bv = *(const float4*)(b1 + u * 64 + jg * 4);
        #pragma unroll
        for (int mm = 0; mm < 8; mm++) {
            float4 h;
            h.x = fmaxf(acc[mm][u*4+0] + bv.x, 0.f);
            h.y = fmaxf(acc[mm][u*4+1] + bv.y, 0.f);
            h.z = fmaxf(acc[mm][u*4+2] + bv.z, 0.f);
            h.w = fmaxf(acc[mm][u*4+3] + bv.w, 0.f);
            *(float4*)(buf + (mg * 8 + mm) * PITCH + u * 64 + jg * 4) = h;
        }
    }

    // ================= layer 2: Z = H @ W2^T + b2 =================
    #pragma unroll
    for (int mm = 0; mm < 8; mm++)
        #pragma unroll
        for (int jj = 0; jj < 16; jj++) acc[mm][jj] = 0.f;

    for (int kc = 0; kc < D; kc += KC) {
        __syncthreads();   // covers H writes on first iter, Wc reuse after
        for (int idx = tid; idx < (KC * D) / 4; idx += PROJ_THREADS)
            ((float4*)Wc)[idx] = ((const float4*)(g_W2T + kc * D))[idx];
        __syncthreads();
        #pragma unroll 2
        for (int k = 0; k < KC; k++) {
            float a[8];
            #pragma unroll
            for (int mm = 0; mm < 8; mm++)
                a[mm] = buf[(mg * 8 + mm) * PITCH + kc + k];
            #pragma unroll
            for (int u = 0; u < 4; u++) {
                float4 b4 = *(const float4*)(Wc + k * D + u * 64 + jg * 4);
                #pragma unroll
                for (int mm = 0; mm < 8; mm++) {
                    acc[mm][u*4+0] = fmaf(a[mm], b4.x, acc[mm][u*4+0]);
                    acc[mm][u*4+1] = fmaf(a[mm], b4.y, acc[mm][u*4+1]);
                    acc[mm][u*4+2] = fmaf(a[mm], b4.z, acc[mm][u*4+2]);
                    acc[mm][u*4+3] = fmaf(a[mm], b4.w, acc[mm][u*4+3]);
                }
            }
        }
    }

    // epilogue 2: bias + L2 normalize + store to g_proj
    float4 b2v[4];
    #pragma unroll
    for (int u = 0; u < 4; u++)
        b2v[u] = *(const float4*)(b2 + u * 64 + jg * 4);

    #pragma unroll
    for (int mm = 0; mm < 8; mm++) {
        float z[16];
        #pragma unroll
        for (int u = 0; u < 4; u++) {
            z[u*4+0] = acc[mm][u*4+0] + b2v[u].x;
            z[u*4+1] = acc[mm][u*4+1] + b2v[u].y;
            z[u*4+2] = acc[mm][u*4+2] + b2v[u].z;
            z[u*4+3] = acc[mm][u*4+3] + b2v[u].w;
        }
        float ss = 0.f;
        #pragma unroll
        for (int jj = 0; jj < 16; jj++) ss += z[jj] * z[jj];
        // reduce across the 16 lanes owning this row (jg group)
        ss += __shfl_xor_sync(0xffffffffu, ss, 1);
        ss += __shfl_xor_sync(0xffffffffu, ss, 2);
        ss += __shfl_xor_sync(0xffffffffu, ss, 4);
        ss += __shfl_xor_sync(0xffffffffu, ss, 8);
        float inv = 1.0f / fmaxf(sqrtf(ss), 1e-12f);

        int r = r0 + mg * 8 + mm;
        if (r < TOTAL_ROWS) {
            float* dst = g_proj + (size_t)r * D;
            #pragma unroll
            for (int u = 0; u < 4; u++) {
                float4 o;
                o.x = z[u*4+0] * inv;
                o.y = z[u*4+1] * inv;
                o.z = z[u*4+2] * inv;
                o.w = z[u*4+3] * inv;
                *(float4*)(dst + u * 64 + jg * 4) = o;
            }
        }
    }
}

// ---------------------------------------------------------------------------
// Warp-collective: exp(2 * dot(z, row)) over D=256
__device__ __forceinline__ float dot_exp(const float4 z0, const float4 z1,
                                         const float* __restrict__ row, int lane)
{
    float4 a = ((const float4*)row)[lane * 2];
    float4 b = ((const float4*)row)[lane * 2 + 1];
    float d = z0.x*a.x + z0.y*a.y + z0.z*a.z + z0.w*a.w
            + z1.x*b.x + z1.y*b.y + z1.z*b.z + z1.w*b.w;
    d += __shfl_xor_sync(0xffffffffu, d, 16);
    d += __shfl_xor_sync(0xffffffffu, d, 8);
    d += __shfl_xor_sync(0xffffffffu, d, 4);
    d += __shfl_xor_sync(0xffffffffu, d, 2);
    d += __shfl_xor_sync(0xffffffffu, d, 1);
    return __expf(2.0f * d);   // 1/TEMP = 2
}

// One warp per anchor. Grid decode:
//   t0: blocks [0,78)   = 6 vl * 13 groups (S=100)
//   t1: blocks [78,156)
//   t2: blocks [156,174)= 6 vl * 3 groups  (S=20)
//   t3: blocks [174,192)
__global__ void __launch_bounds__(256) loss_kernel(float* __restrict__ out)
{
    int b = blockIdx.x;
    int t, rb, S, K, G, qbase, pbase;
    if (b < 78)       { t=0; rb=b;     S=100; K=50; G=13; qbase=0;    pbase=0;    }
    else if (b < 156) { t=1; rb=b-78;  S=100; K=50; G=13; qbase=3600; pbase=900;  }
    else if (b < 174) { t=2; rb=b-156; S=20;  K=10; G=3;  qbase=7200; pbase=1800; }
    else              { t=3; rb=b-174; S=20;  K=10; G=3;  qbase=7920; pbase=1980; }
    (void)t;
    int vl = rb / G, sg = rb - vl * G;
    int wid  = threadIdx.x >> 5;
    int lane = threadIdx.x & 31;
    int s = sg * 8 + wid;
    if (s >= S) return;

    const float* Q = g_proj + (size_t)qbase * D;
    const float* P = g_proj + (size_t)(Q_ROWS + pbase) * D;

    const float* zrow = Q + (size_t)((vl * 6 + vl) * S + s) * D;
    float4 z0 = ((const float4*)zrow)[lane * 2];
    float4 z1 = ((const float4*)zrow)[lane * 2 + 1];

    // positives: same node at every other (x,y)
    float pos = 0.f;
    #pragma unroll
    for (int xy = 0; xy < 6; xy++) {
        if (xy == vl) continue;
        pos += dot_exp(z0, z1, Q + (size_t)((xy * 6 + vl) * S + s) * D, lane);
    }

    // within-type negatives: other anchors at same (v,l)
    float neg = 0.f;
    const float* zb = Q + (size_t)((vl * 6 + vl) * S) * D;
    #pragma unroll 4
    for (int tp = 0; tp < S; tp++) {
        if (tp == s) continue;
        neg += dot_exp(z0, z1, zb + (size_t)tp * D, lane);
    }

    // cross-type negatives
    for (int o = 0; o < 3; o++) {
        const float* pb = P + (size_t)((o * 6 + vl) * K) * D;
        #pragma unroll 5
        for (int k = 0; k < K; k++)
            neg += dot_exp(z0, z1, pb + (size_t)k * D, lane);
    }

    float loss = -logf(pos / (pos + neg));
    if (lane == 0) atomicAdd(out, loss * (1.0f / 1440.0f));
}

// ---------------------------------------------------------------------------
extern "C" void kernel_launch(void* const* d_in, const int* in_sizes, int n_in,
                              void* d_out, int out_size)
{
    const float* E    = (const float*)d_in[0];   // [4,2,3,4000,256]
    const float* W1   = (const float*)d_in[1];   // [256,256]
    const float* b1   = (const float*)d_in[2];   // [256]
    const float* W2   = (const float*)d_in[3];   // [256,256]
    const float* b2   = (const float*)d_in[4];   // [256]
    const int*   idxp = (const int*)d_in[5];     // [2,2,3,100]
    const int*   idxr = (const int*)d_in[6];     // [2,2,3,20]
    const int*   negp = (const int*)d_in[7];     // [2,2,3,3,50]
    const int*   negr = (const int*)d_in[8];     // [2,2,3,3,10]
    float* out = (float*)d_out;
    (void)in_sizes; (void)n_in; (void)out_size;

    size_t shmem = (size_t)(TM * PITCH + KC * D) * sizeof(float)
                 + TM * sizeof(float*);
    cudaFuncSetAttribute(proj_kernel,
                         cudaFuncAttributeMaxDynamicSharedMemorySize,
                         (int)shmem);

    zero_out_kernel<<<1, 1>>>(out);
    transpose_kernel<<<512, 256>>>(W1, W2);
    proj_kernel<<<PROJ_BLOCKS, PROJ_THREADS, shmem>>>(E, b1, b2,
                                                      idxp, idxr, negp, negr);
    loss_kernel<<<192, 256>>>(out);
}

// round 2
// speedup vs baseline: 1.0430x; 1.0430x over previous
#include <cuda_runtime.h>
#include <math.h>

// Problem constants
#define D        256
#define N_NODES  4000
#define LL       3     // layers
#define VV       2     // views

// Gathered-row scratch layout:
//  Q region  : rows [0, 8640)  -- per type t: base_t + (xy*6 + vl)*S_t + s
//  Pneg region: rows [8640, 10800) -- per type t: pbase_t + (o*6 + vl)*K_t + k
#define Q_ROWS     8640
#define PNEG_ROWS  2160
#define TOTAL_ROWS 10800
#define N_ANCHORS  1440

#define TM            64
#define PITCH         260
#define KC            32
#define PROJ_THREADS  128
#define PROJ_BLOCKS   169          // ceil(10800/64)

__device__ float g_proj[(size_t)PROJ_BLOCKS * TM * D];   // 11.1 MB scratch
__device__ float g_W1T[D * D];
__device__ float g_W2T[D * D];
__device__ float g_pos[N_ANCHORS];
__device__ float g_neg[N_ANCHORS];

// ---------------------------------------------------------------------------
__global__ void zero_kernel(float* out)
{
    int i = blockIdx.x * blockDim.x + threadIdx.x;
    if (i < N_ANCHORS) { g_pos[i] = 0.f; g_neg[i] = 0.f; }
    if (i == 0) out[0] = 0.f;
}

// Transpose both weight matrices: WT[k][j] = W[j][k]
__global__ void transpose_kernel(const float* __restrict__ W1,
                                 const float* __restrict__ W2)
{
    int i = blockIdx.x * blockDim.x + threadIdx.x;   // 0 .. 131071
    int half = i >> 16;
    int r = i & 65535;
    int k = r >> 8, j = r & 255;
    if (half == 0) g_W1T[(k << 8) + j] = W1[(j << 8) + k];
    else           g_W2T[(k << 8) + j] = W2[(j << 8) + k];
}

// ---------------------------------------------------------------------------
// Map a global gathered-row id -> source embedding row pointer
__device__ __forceinline__ const float* map_src_row(
    int r, const float* __restrict__ E,
    const int* __restrict__ idxp, const int* __restrict__ idxr,
    const int* __restrict__ negp, const int* __restrict__ negr)
{
    if (r < Q_ROWS) {
        int t, local, S;
        if (r < 3600)      { t = 0; local = r;        S = 100; }
        else if (r < 7200) { t = 1; local = r - 3600; S = 100; }
        else if (r < 7920) { t = 2; local = r - 7200; S = 20;  }
        else               { t = 3; local = r - 7920; S = 20;  }
        int perxy = 6 * S;
        int xy  = local / perxy;
        int rem = local - xy * perxy;
        int node = (t < 2) ? idxp[t * 600 + rem] : idxr[(t - 2) * 120 + rem];
        int x = xy / LL, y = xy - x * LL;
        return E + ((size_t)(((t * VV + x) * LL + y) * N_NODES + node)) * D;
    } else {
        int rr = r - Q_ROWS;
        int t, local, K;
        if (rr < 900)       { t = 0; local = rr;        K = 50; }
        else if (rr < 1800) { t = 1; local = rr - 900;  K = 50; }
        else if (rr < 1980) { t = 2; local = rr - 1800; K = 10; }
        else                { t = 3; local = rr - 1980; K = 10; }
        int perO = 6 * K;
        int o   = local / perO;
        int vlk = local - o * perO;
        int vl  = vlk / K;
        int k   = vlk - vl * K;
        int off = (vl * 3 + o) * K + k;
        int node = (t < 2) ? negp[t * 900 + off] : negr[(t - 2) * 180 + off];
        int ot = o + (o >= t ? 1 : 0);
        int v = vl / LL, l = vl - v * LL;
        return E + ((size_t)(((ot * VV + v) * LL + l) * N_NODES + node)) * D;
    }
}

// ---------------------------------------------------------------------------
// Gather + 2-layer MLP (relu) + L2 normalize. One block per 64 rows.
__global__ void __launch_bounds__(PROJ_THREADS)
proj_kernel(const float* __restrict__ E,
            const float* __restrict__ b1, const float* __restrict__ b2,
            const int* __restrict__ idxp, const int* __restrict__ idxr,
            const int* __restrict__ negp, const int* __restrict__ negr)
{
    extern __shared__ float sm[];
    float* buf = sm;                          // [TM][PITCH]
    float* Wc  = sm + TM * PITCH;             // [KC][D]
    const float** srcp = (const float**)(Wc + KC * D);

    const int tid = threadIdx.x;
    const int jg  = tid & 15;
    const int mg  = tid >> 4;
    const int r0  = blockIdx.x * TM;

    if (tid < TM) {
        int r = r0 + tid;
        srcp[tid] = (r < TOTAL_ROWS)
                  ? map_src_row(r, E, idxp, idxr, negp, negr)
                  : (const float*)0;
    }
    __syncthreads();

    for (int idx = tid; idx < TM * 64; idx += PROJ_THREADS) {
        int m = idx >> 6, q = idx & 63;
        const float* s = srcp[m];
        float4 v = make_float4(0.f, 0.f, 0.f, 0.f);
        if (s) v = ((const float4*)s)[q];
        *(float4*)(buf + m * PITCH + 4 * q) = v;
    }

    float acc[8][16];

    // layer 1
    #pragma unroll
    for (int mm = 0; mm < 8; mm++)
        #pragma unroll
        for (int jj = 0; jj < 16; jj++) acc[mm][jj] = 0.f;

    for (int kc = 0; kc < D; kc += KC) {
        __syncthreads();
        for (int idx = tid; idx < (KC * D) / 4; idx += PROJ_THREADS)
            ((float4*)Wc)[idx] = ((const float4*)(g_W1T + kc * D))[idx];
        __syncthreads();
        #pragma unroll 2
        for (int k = 0; k < KC; k++) {
            float a[8];
            #pragma unroll
            for (int mm = 0; mm < 8; mm++)
                a[mm] = buf[(mg * 8 + mm) * PITCH + kc + k];
            #pragma unroll
            for (int u = 0; u < 4; u++) {
                float4 b4 = *(const float4*)(Wc + k * D + u * 64 + jg * 4);
                #pragma unroll
                for (int mm = 0; mm < 8; mm++) {
                    acc[mm][u*4+0] = fmaf(a[mm], b4.x, acc[mm][u*4+0]);
                    acc[mm][u*4+1] = fmaf(a[mm], b4.y, acc[mm][u*4+1]);
                    acc[mm][u*4+2] = fmaf(a[mm], b4.z, acc[mm][u*4+2]);
                    acc[mm][u*4+3] = fmaf(a[mm], b4.w, acc[mm][u*4+3]);
                }
            }
        }
    }
    __syncthreads();

    #pragma unroll
    for (int u = 0; u < 4; u++) {
        float4 bv = *(const float4*)(b1 + u * 64 + jg * 4);
        #pragma unroll
        for (int mm = 0; mm < 8; mm++) {
            float4 h;
            h.x = fmaxf(acc[mm][u*4+0] + bv.x, 0.f);
            h.y = fmaxf(acc[mm][u*4+1] + bv.y, 0.f);
            h.z = fmaxf(acc[mm][u*4+2] + bv.z, 0.f);
            h.w = fmaxf(acc[mm][u*4+3] + bv.w, 0.f);
            *(float4*)(buf + (mg * 8 + mm) * PITCH + u * 64 + jg * 4) = h;
        }
    }

    // layer 2
    #pragma unroll
    for (int mm = 0; mm < 8; mm++)
        #pragma unroll
        for (int jj = 0; jj < 16; jj++) acc[mm][jj] = 0.f;

    for (int kc = 0; kc < D; kc += KC) {
        __syncthreads();
        for (int idx = tid; idx < (KC * D) / 4; idx += PROJ_THREADS)
            ((float4*)Wc)[idx] = ((const float4*)(g_W2T + kc * D))[idx];
        __syncthreads();
        #pragma unroll 2
        for (int k = 0; k < KC; k++) {
            float a[8];
            #pragma unroll
            for (int mm = 0; mm < 8; mm++)
                a[mm] = buf[(mg * 8 + mm) * PITCH + kc + k];
            #pragma unroll
            for (int u = 0; u < 4; u++) {
                float4 b4 = *(const float4*)(Wc + k * D + u * 64 + jg * 4);
                #pragma unroll
                for (int mm = 0; mm < 8; mm++) {
                    acc[mm][u*4+0] = fmaf(a[mm], b4.x, acc[mm][u*4+0]);
                    acc[mm][u*4+1] = fmaf(a[mm], b4.y, acc[mm][u*4+1]);
                    acc[mm][u*4+2] = fmaf(a[mm], b4.z, acc[mm][u*4+2]);
                    acc[mm][u*4+3] = fmaf(a[mm], b4.w, acc[mm][u*4+3]);
                }
            }
        }
    }

    float4 b2v[4];
    #pragma unroll
    for (int u = 0; u < 4; u++)
        b2v[u] = *(const float4*)(b2 + u * 64 + jg * 4);

    #pragma unroll
    for (int mm = 0; mm < 8; mm++) {
        float z[16];
        #pragma unroll
        for (int u = 0; u < 4; u++) {
            z[u*4+0] = acc[mm][u*4+0] + b2v[u].x;
            z[u*4+1] = acc[mm][u*4+1] + b2v[u].y;
            z[u*4+2] = acc[mm][u*4+2] + b2v[u].z;
            z[u*4+3] = acc[mm][u*4+3] + b2v[u].w;
        }
        float ss = 0.f;
        #pragma unroll
        for (int jj = 0; jj < 16; jj++) ss += z[jj] * z[jj];
        ss += __shfl_xor_sync(0xffffffffu, ss, 1);
        ss += __shfl_xor_sync(0xffffffffu, ss, 2);
        ss += __shfl_xor_sync(0xffffffffu, ss, 4);
        ss += __shfl_xor_sync(0xffffffffu, ss, 8);
        float inv = 1.0f / fmaxf(sqrtf(ss), 1e-12f);

        int r = r0 + mg * 8 + mm;
        if (r < TOTAL_ROWS) {
            float* dst = g_proj + (size_t)r * D;
            #pragma unroll
            for (int u = 0; u < 4; u++) {
                float4 o;
                o.x = z[u*4+0] * inv;
                o.y = z[u*4+1] * inv;
                o.z = z[u*4+2] * inv;
                o.w = z[u*4+3] * inv;
                *(float4*)(dst + u * 64 + jg * 4) = o;
            }
        }
    }
}

// ---------------------------------------------------------------------------
// Loss sims: register-blocked "GEMM". One block = (type, vl, anchor-tile,
// target-split). A anchors in smem; each thread streams ONE target row and
// accumulates A dots in registers. exp -> smem partials -> warp reduce ->
// atomicAdd into g_neg. Positives (5 per anchor) handled by the tsplit==0
// block with per-thread serial dots.
template <int A, int S, int K, int NT, int TSPL>
__global__ void __launch_bounds__(128)
loss_sims_kernel()
{
    __shared__ float sm_anch[A * 256];
    __shared__ float sm_part[A * 128];

    const int tid  = threadIdx.x;
    const int lane = tid & 31;
    const int wid  = tid >> 5;
    const int b    = blockIdx.x;

    int t, vl, atile, tsplit, qbase, pbase, aid0;
    if (TSPL == 2) {
        // big: 2 types * 6 vl * 4 atiles * 2 splits = 96 blocks
        tsplit = b & 1;
        atile  = (b >> 1) & 3;
        vl     = (b >> 3) % 6;
        t      = b / 48;
        qbase  = t * 3600;
        pbase  = t * 900;
        aid0   = t * 600 + vl * S + atile * A;
    } else {
        // small: 2 types * 6 vl = 12 blocks
        tsplit = 0;
        atile  = 0;
        vl     = b % 6;
        t      = b / 6;               // 0 -> type2, 1 -> type3
        qbase  = 7200 + t * 720;
        pbase  = 1800 + t * 180;
        aid0   = 1200 + t * 120 + vl * S;
    }
    const int abase     = atile * A;
    const int diag_base = qbase + (vl * 6 + vl) * S;   // anchor/gram row base

    // load anchor tile into smem
    for (int i = tid; i < A * 64; i += 128) {
        int a = i >> 6, q = i & 63;
        ((float4*)sm_anch)[a * 64 + q] =
            ((const float4*)(g_proj + (size_t)(diag_base + abase + a) * 256))[q];
    }
    __syncthreads();

    // resolve this thread's target row
    const int cnt = NT / TSPL;
    const int n   = tsplit * cnt + tid;
    const bool active = tid < cnt;
    const float* trow = g_proj;   // dummy (never read when !active)
    int self_a = -1;
    if (active) {
        if (n < S) {
            trow = g_proj + (size_t)(diag_base + n) * 256;
            int sa = n - abase;
            if (sa >= 0 && sa < A) self_a = sa;
        } else {
            int c = n - S;
            int o = c / K, k = c - o * K;
            trow = g_proj + (size_t)(Q_ROWS + pbase + (o * 6 + vl) * K + k) * 256;
        }
    }

    float racc[A];
    #pragma unroll
    for (int a = 0; a < A; a++) racc[a] = 0.f;

    if (active) {
        const float4* t4p = (const float4*)trow;
        #pragma unroll 2
        for (int q = 0; q < 64; q++) {
            float4 t4 = t4p[q];
            #pragma unroll
            for (int a = 0; a < A; a++) {
                float4 a4 = ((const float4*)sm_anch)[a * 64 + q];
                float d = fmaf(t4.x, a4.x, fmaf(t4.y, a4.y,
                          fmaf(t4.z, a4.z, t4.w * a4.w)));
                racc[a] += d;
            }
        }
    }

    // exp + stash partials (self term excluded from neg)
    #pragma unroll
    for (int a = 0; a < A; a++) {
        float v = (active && a != self_a) ? __expf(2.0f * racc[a]) : 0.f;
        sm_part[a * 128 + tid] = v;
    }
    __syncthreads();

    // per-anchor reduce over 128 threads (4 warps cover A anchors)
    for (int a = wid; a < A; a += 4) {
        const float* row = sm_part + a * 128;
        float s = row[lane] + row[lane + 32] + row[lane + 64] + row[lane + 96];
        s += __shfl_xor_sync(0xffffffffu, s, 16);
        s += __shfl_xor_sync(0xffffffffu, s, 8);
        s += __shfl_xor_sync(0xffffffffu, s, 4);
        s += __shfl_xor_sync(0xffffffffu, s, 2);
        s += __shfl_xor_sync(0xffffffffu, s, 1);
        if (lane == 0) atomicAdd(&g_neg[aid0 + a], s);
    }

    // positives: 5 per anchor, only in the tsplit==0 block
    if (tsplit == 0 && tid < A * 5) {
        int a = tid / 5, p = tid - a * 5;
        int xy = p + (p >= vl ? 1 : 0);
        const float4* pr = (const float4*)
            (g_proj + (size_t)(qbase + (xy * 6 + vl) * S + abase + a) * 256);
        const float4* ar = (const float4*)(sm_anch + a * 256);
        float d = 0.f;
        #pragma unroll 4
        for (int q = 0; q < 64; q++) {
            float4 x = pr[q], y = ar[q];
            d += x.x*y.x + x.y*y.y + x.z*y.z + x.w*y.w;
        }
        atomicAdd(&g_pos[aid0 + a], __expf(2.0f * d));
    }
}

// ---------------------------------------------------------------------------
__global__ void __launch_bounds__(256) finalize_kernel(float* __restrict__ out)
{
    int i = blockIdx.x * 256 + threadIdx.x;
    float loss = 0.f;
    if (i < N_ANCHORS) {
        float p = g_pos[i], n = g_neg[i];
        loss = -logf(p / (p + n));
    }
    loss += __shfl_xor_sync(0xffffffffu, loss, 16);
    loss += __shfl_xor_sync(0xffffffffu, loss, 8);
    loss += __shfl_xor_sync(0xffffffffu, loss, 4);
    loss += __shfl_xor_sync(0xffffffffu, loss, 2);
    loss += __shfl_xor_sync(0xffffffffu, loss, 1);
    __shared__ float wsum[8];
    int lane = threadIdx.x & 31, wid = threadIdx.x >> 5;
    if (lane == 0) wsum[wid] = loss;
    __syncthreads();
    if (wid == 0) {
        float s = (lane < 8) ? wsum[lane] : 0.f;
        s += __shfl_xor_sync(0xffffffffu, s, 4);
        s += __shfl_xor_sync(0xffffffffu, s, 2);
        s += __shfl_xor_sync(0xffffffffu, s, 1);
        if (lane == 0) atomicAdd(out, s * (1.0f / 1440.0f));
    }
}

// ---------------------------------------------------------------------------
extern "C" void kernel_launch(void* const* d_in, const int* in_sizes, int n_in,
                              void* d_out, int out_size)
{
    const float* E    = (const float*)d_in[0];   // [4,2,3,4000,256]
    const float* W1   = (const float*)d_in[1];   // [256,256]
    const float* b1   = (const float*)d_in[2];   // [256]
    const float* W2   = (const float*)d_in[3];   // [256,256]
    const float* b2   = (const float*)d_in[4];   // [256]
    const int*   idxp = (const int*)d_in[5];     // [2,2,3,100]
    const int*   idxr = (const int*)d_in[6];     // [2,2,3,20]
    const int*   negp = (const int*)d_in[7];     // [2,2,3,3,50]
    const int*   negr = (const int*)d_in[8];     // [2,2,3,3,10]
    float* out = (float*)d_out;
    (void)in_sizes; (void)n_in; (void)out_size;

    size_t shmem = (size_t)(TM * PITCH + KC * D) * sizeof(float)
                 + TM * sizeof(float*);
    cudaFuncSetAttribute(proj_kernel,
                         cudaFuncAttributeMaxDynamicSharedMemorySize,
                         (int)shmem);

    zero_kernel<<<6, 256>>>(out);
    transpose_kernel<<<512, 256>>>(W1, W2);
    proj_kernel<<<PROJ_BLOCKS, PROJ_THREADS, shmem>>>(E, b1, b2,
                                                      idxp, idxr, negp, negr);
    loss_sims_kernel<25, 100, 50, 250, 2><<<96, 128>>>();
    loss_sims_kernel<20,  20, 10,  50, 1><<<12, 128>>>();
    finalize_kernel<<<6, 256>>>(out);
}

// round 4
// speedup vs baseline: 2.3326x; 2.2364x over previous
#include <cuda_runtime.h>
#include <cuda_fp16.h>
#include <math.h>
#include <stdint.h>

// ---------------------------------------------------------------------------
#define D        256
#define N_NODES  4000
#define LL       3
#define VV       2

#define Q_ROWS     8640
#define TOTAL_ROWS 10800
#define N_ANCHORS  1440

#define PROJ_BLOCKS 85      // ceil(10800 / 128)
#define ROWS_PB     128

__device__ float g_proj[(size_t)PROJ_BLOCKS * ROWS_PB * D];  // 11.1 MB
__device__ unsigned int g_Wh[2][32768];   // fp16 W1/W2, row-major [n][k]
__device__ float g_pos[N_ANCHORS];
__device__ float g_neg[N_ANCHORS];

// ---------------------------------------------------------------------------
__device__ __forceinline__ uint32_t smem_u32(const void* p) {
    uint32_t a;
    asm("{ .reg .u64 t; cvta.to.shared.u64 t, %1; cvt.u32.u64 %0, t; }"
        : "=r"(a) : "l"(p));
    return a;
}
__device__ __forceinline__ void ldsm_x4(uint32_t* r, uint32_t addr) {
    asm volatile("ldmatrix.sync.aligned.m8n8.x4.shared.b16 {%0,%1,%2,%3}, [%4];"
                 : "=r"(r[0]), "=r"(r[1]), "=r"(r[2]), "=r"(r[3]) : "r"(addr));
}
__device__ __forceinline__ void ldsm_x2(uint32_t* r, uint32_t addr) {
    asm volatile("ldmatrix.sync.aligned.m8n8.x2.shared.b16 {%0,%1}, [%2];"
                 : "=r"(r[0]), "=r"(r[1]) : "r"(addr));
}
__device__ __forceinline__ void mma16816(float* c, const uint32_t* a,
                                         const uint32_t* b) {
    asm volatile("mma.sync.aligned.m16n8k16.row.col.f32.f16.f16.f32 "
                 "{%0,%1,%2,%3}, {%4,%5,%6,%7}, {%8,%9}, {%0,%1,%2,%3};"
                 : "+f"(c[0]), "+f"(c[1]), "+f"(c[2]), "+f"(c[3])
                 : "r"(a[0]), "r"(a[1]), "r"(a[2]), "r"(a[3]),
                   "r"(b[0]), "r"(b[1]));
}

// ---------------------------------------------------------------------------
__global__ void zero_kernel(float* out)
{
    int i = blockIdx.x * blockDim.x + threadIdx.x;
    if (i < N_ANCHORS) { g_pos[i] = 0.f; g_neg[i] = 0.f; }
    if (i == 0) out[0] = 0.f;
}

// fp32 W -> fp16 row-major image
__global__ void prep_w_kernel(const float* __restrict__ W1,
                              const float* __restrict__ W2)
{
    int i = blockIdx.x * blockDim.x + threadIdx.x;   // 0..65535
    int which = i >> 15;
    int r = i & 32767;                                // half2 index
    const float* W = which ? W2 : W1;
    __half2 h = __floats2half2_rn(W[r * 2], W[r * 2 + 1]);
    g_Wh[which][r] = *reinterpret_cast<unsigned int*>(&h);
}

// ---------------------------------------------------------------------------
__device__ __forceinline__ const float* map_src_row(
    int r, const float* __restrict__ E,
    const int* __restrict__ idxp, const int* __restrict__ idxr,
    const int* __restrict__ negp, const int* __restrict__ negr)
{
    if (r < Q_ROWS) {
        int t, local, S;
        if (r < 3600)      { t = 0; local = r;        S = 100; }
        else if (r < 7200) { t = 1; local = r - 3600; S = 100; }
        else if (r < 7920) { t = 2; local = r - 7200; S = 20;  }
        else               { t = 3; local = r - 7920; S = 20;  }
        int perxy = 6 * S;
        int xy  = local / perxy;
        int rem = local - xy * perxy;
        int node = (t < 2) ? idxp[t * 600 + rem] : idxr[(t - 2) * 120 + rem];
        int x = xy / LL, y = xy - x * LL;
        return E + ((size_t)(((t * VV + x) * LL + y) * N_NODES + node)) * D;
    } else {
        int rr = r - Q_ROWS;
        int t, local, K;
        if (rr < 900)       { t = 0; local = rr;        K = 50; }
        else if (rr < 1800) { t = 1; local = rr - 900;  K = 50; }
        else if (rr < 1980) { t = 2; local = rr - 1800; K = 10; }
        else                { t = 3; local = rr - 1980; K = 10; }
        int perO = 6 * K;
        int o   = local / perO;
        int vlk = local - o * perO;
        int vl  = vlk / K;
        int k   = vlk - vl * K;
        int off = (vl * 3 + o) * K + k;
        int node = (t < 2) ? negp[t * 900 + off] : negr[(t - 2) * 180 + off];
        int ot = o + (o >= t ? 1 : 0);
        int v = vl / LL, l = vl - v * LL;
        return E + ((size_t)(((ot * VV + v) * LL + l) * N_NODES + node)) * D;
    }
}

// ---------------------------------------------------------------------------
// smem layout (bytes): A tile fp16 128x264 @0, W tile fp16 256x264 @67584,
// ctrl @202752: b1[256]f32 @+0, b2 @+1024, srcp[128] @+2048, ssbuf[128][4] @+3072
#define SMA   0
#define SMW   67584
#define CTRL  202752
#define SM_BYTES (CTRL + 3072 + 2048)

#define APITCH 264

__global__ void __launch_bounds__(512, 1)
proj_mma_kernel(const float* __restrict__ E,
                const float* __restrict__ b1, const float* __restrict__ b2,
                const int* __restrict__ idxp, const int* __restrict__ idxr,
                const int* __restrict__ negp, const int* __restrict__ negr)
{
    extern __shared__ char sm[];
    const uint32_t smb = smem_u32(sm);

    float* smb1 = (float*)(sm + CTRL);
    float* smb2 = (float*)(sm + CTRL + 1024);
    const float** srcp = (const float**)(sm + CTRL + 2048);
    float* ssbuf = (float*)(sm + CTRL + 3072);

    const int tid = threadIdx.x;
    const int l   = tid & 31;
    const int w   = tid >> 5;
    const int my  = w >> 2;          // 0..3  : rows 32*my
    const int cx  = w & 3;           // 0..3  : cols 64*cx
    const int r0  = blockIdx.x * ROWS_PB;

    if (tid < 64)        ((float4*)smb1)[tid]      = ((const float4*)b1)[tid];
    else if (tid < 128)  ((float4*)smb2)[tid - 64] = ((const float4*)b2)[tid - 64];
    if (tid < ROWS_PB) {
        int r = r0 + tid;
        srcp[tid] = (r < TOTAL_ROWS)
                  ? map_src_row(r, E, idxp, idxr, negp, negr)
                  : (const float*)0;
    }

    // W1 -> smem (padded pitch)
    for (int i = tid; i < 8192; i += 512) {
        int n = i >> 5, q = i & 31;
        *(float4*)(sm + SMW + (n * APITCH + q * 8) * 2) = ((const float4*)g_Wh[0])[i];
    }
    __syncthreads();

    // gather X -> fp16 A tile
    for (int i = tid; i < ROWS_PB * 64; i += 512) {
        int m = i >> 6, q = i & 63;
        const float* s = srcp[m];
        float4 v = make_float4(0.f, 0.f, 0.f, 0.f);
        if (s) v = ((const float4*)s)[q];
        __half2 p0 = __floats2half2_rn(v.x, v.y);
        __half2 p1 = __floats2half2_rn(v.z, v.w);
        uint2 pk = make_uint2(*reinterpret_cast<unsigned int*>(&p0),
                              *reinterpret_cast<unsigned int*>(&p1));
        *(uint2*)(sm + SMA + (m * APITCH + q * 4) * 2) = pk;
    }
    __syncthreads();

    // ldmatrix base addresses
    const uint32_t a_base = smb + SMA +
        ((my * 32 + ((l >> 3) & 1) * 8 + (l & 7)) * APITCH + (l >> 4) * 8) * 2;
    const uint32_t b_base = smb + SMW +
        ((cx * 64 + (l & 7)) * APITCH + ((l >> 3) & 1) * 8) * 2;

    float c[2][8][4];

    // ================= layer 1 =================
    #pragma unroll
    for (int mt = 0; mt < 2; mt++)
        #pragma unroll
        for (int nt = 0; nt < 8; nt++)
            #pragma unroll
            for (int j = 0; j < 4; j++) c[mt][nt][j] = 0.f;

    #pragma unroll 4
    for (int kk = 0; kk < 16; kk++) {
        uint32_t a[8];
        ldsm_x4(a,     a_base + kk * 32);
        ldsm_x4(a + 4, a_base + kk * 32 + 16 * APITCH * 2);
        #pragma unroll
        for (int nt = 0; nt < 8; nt++) {
            uint32_t b[2];
            ldsm_x2(b, b_base + kk * 32 + nt * 8 * APITCH * 2);
            mma16816(c[0][nt], a,     b);
            mma16816(c[1][nt], a + 4, b);
        }
    }
    __syncthreads();   // A reads done, safe to overwrite

    // epilogue 1: bias+relu -> fp16 H into A tile
    const int g  = l >> 2;
    const int q2 = (l & 3) * 2;
    #pragma unroll
    for (int mt = 0; mt < 2; mt++) {
        #pragma unroll
        for (int nt = 0; nt < 8; nt++) {
            int col = cx * 64 + nt * 8 + q2;
            float bx = smb1[col], by = smb1[col + 1];
            int rlo = my * 32 + mt * 16 + g;
            __half2 lo = __floats2half2_rn(fmaxf(c[mt][nt][0] + bx, 0.f),
                                           fmaxf(c[mt][nt][1] + by, 0.f));
            __half2 hi = __floats2half2_rn(fmaxf(c[mt][nt][2] + bx, 0.f),
                                           fmaxf(c[mt][nt][3] + by, 0.f));
            *(unsigned int*)(sm + SMA + (rlo * APITCH + col) * 2) =
                *reinterpret_cast<unsigned int*>(&lo);
            *(unsigned int*)(sm + SMA + ((rlo + 8) * APITCH + col) * 2) =
                *reinterpret_cast<unsigned int*>(&hi);
        }
    }
    // W2 -> smem
    for (int i = tid; i < 8192; i += 512) {
        int n = i >> 5, q = i & 31;
        *(float4*)(sm + SMW + (n * APITCH + q * 8) * 2) = ((const float4*)g_Wh[1])[i];
    }
    __syncthreads();

    // ================= layer 2 =================
    #pragma unroll
    for (int mt = 0; mt < 2; mt++)
        #pragma unroll
        for (int nt = 0; nt < 8; nt++)
            #pragma unroll
            for (int j = 0; j < 4; j++) c[mt][nt][j] = 0.f;

    #pragma unroll 4
    for (int kk = 0; kk < 16; kk++) {
        uint32_t a[8];
        ldsm_x4(a,     a_base + kk * 32);
        ldsm_x4(a + 4, a_base + kk * 32 + 16 * APITCH * 2);
        #pragma unroll
        for (int nt = 0; nt < 8; nt++) {
            uint32_t b[2];
            ldsm_x2(b, b_base + kk * 32 + nt * 8 * APITCH * 2);
            mma16816(c[0][nt], a,     b);
            mma16816(c[1][nt], a + 4, b);
        }
    }

    // epilogue 2: bias, row sum-of-squares, normalize, store
    float ss[4] = {0.f, 0.f, 0.f, 0.f};
    #pragma unroll
    for (int mt = 0; mt < 2; mt++) {
        #pragma unroll
        for (int nt = 0; nt < 8; nt++) {
            int col = cx * 64 + nt * 8 + q2;
            float bx = smb2[col], by = smb2[col + 1];
            float z0 = c[mt][nt][0] + bx, z1 = c[mt][nt][1] + by;
            float z2 = c[mt][nt][2] + bx, z3 = c[mt][nt][3] + by;
            ss[mt * 2]     += z0 * z0 + z1 * z1;
            ss[mt * 2 + 1] += z2 * z2 + z3 * z3;
        }
    }
    #pragma unroll
    for (int j = 0; j < 4; j++) {
        ss[j] += __shfl_xor_sync(0xffffffffu, ss[j], 1);
        ss[j] += __shfl_xor_sync(0xffffffffu, ss[j], 2);
    }
    if ((l & 3) == 0) {
        #pragma unroll
        for (int j = 0; j < 4; j++) {
            int row = my * 32 + (j >> 1) * 16 + (j & 1) * 8 + g;
            ssbuf[row * 4 + cx] = ss[j];
        }
    }
    __syncthreads();

    float inv[4];
    #pragma unroll
    for (int j = 0; j < 4; j++) {
        int row = my * 32 + (j >> 1) * 16 + (j & 1) * 8 + g;
        float t = ssbuf[row * 4 + 0] + ssbuf[row * 4 + 1]
                + ssbuf[row * 4 + 2] + ssbuf[row * 4 + 3];
        inv[j] = 1.0f / fmaxf(sqrtf(t), 1e-12f);
    }

    #pragma unroll
    for (int mt = 0; mt < 2; mt++) {
        #pragma unroll
        for (int nt = 0; nt < 8; nt++) {
            int col = cx * 64 + nt * 8 + q2;
            float bx = smb2[col], by = smb2[col + 1];
            int rlo = r0 + my * 32 + mt * 16 + g;
            int rhi = rlo + 8;
            if (rlo < TOTAL_ROWS) {
                float2 o = make_float2((c[mt][nt][0] + bx) * inv[mt * 2],
                                       (c[mt][nt][1] + by) * inv[mt * 2]);
                *(float2*)(g_proj + (size_t)rlo * D + col) = o;
            }
            if (rhi < TOTAL_ROWS) {
                float2 o = make_float2((c[mt][nt][2] + bx) * inv[mt * 2 + 1],
                                       (c[mt][nt][3] + by) * inv[mt * 2 + 1]);
                *(float2*)(g_proj + (size_t)rhi * D + col) = o;
            }
        }
    }
}

// ---------------------------------------------------------------------------
// Loss sims (unchanged from R2)
template <int A, int S, int K, int NT, int TSPL>
__global__ void __launch_bounds__(128)
loss_sims_kernel()
{
    __shared__ float sm_anch[A * 256];
    __shared__ float sm_part[A * 128];

    const int tid  = threadIdx.x;
    const int lane = tid & 31;
    const int wid  = tid >> 5;
    const int b    = blockIdx.x;

    int t, vl, atile, tsplit, qbase, pbase, aid0;
    if (TSPL == 2) {
        tsplit = b & 1;
        atile  = (b >> 1) & 3;
        vl     = (b >> 3) % 6;
        t      = b / 48;
        qbase  = t * 3600;
        pbase  = t * 900;
        aid0   = t * 600 + vl * S + atile * A;
    } else {
        tsplit = 0;
        atile  = 0;
        vl     = b % 6;
        t      = b / 6;
        qbase  = 7200 + t * 720;
        pbase  = 1800 + t * 180;
        aid0   = 1200 + t * 120 + vl * S;
    }
    const int abase     = atile * A;
    const int diag_base = qbase + (vl * 6 + vl) * S;

    for (int i = tid; i < A * 64; i += 128) {
        int a = i >> 6, q = i & 63;
        ((float4*)sm_anch)[a * 64 + q] =
            ((const float4*)(g_proj + (size_t)(diag_base + abase + a) * 256))[q];
    }
    __syncthreads();

    const int cnt = NT / TSPL;
    const int n   = tsplit * cnt + tid;
    const bool active = tid < cnt;
    const float* trow = g_proj;
    int self_a = -1;
    if (active) {
        if (n < S) {
            trow = g_proj + (size_t)(diag_base + n) * 256;
            int sa = n - abase;
            if (sa >= 0 && sa < A) self_a = sa;
        } else {
            int c = n - S;
            int o = c / K, k = c - o * K;
            trow = g_proj + (size_t)(Q_ROWS + pbase + (o * 6 + vl) * K + k) * 256;
        }
    }

    float racc[A];
    #pragma unroll
    for (int a = 0; a < A; a++) racc[a] = 0.f;

    if (active) {
        const float4* t4p = (const float4*)trow;
        #pragma unroll 2
        for (int q = 0; q < 64; q++) {
            float4 t4 = t4p[q];
            #pragma unroll
            for (int a = 0; a < A; a++) {
                float4 a4 = ((const float4*)sm_anch)[a * 64 + q];
                float d = fmaf(t4.x, a4.x, fmaf(t4.y, a4.y,
                          fmaf(t4.z, a4.z, t4.w * a4.w)));
                racc[a] += d;
            }
        }
    }

    #pragma unroll
    for (int a = 0; a < A; a++) {
        float v = (active && a != self_a) ? __expf(2.0f * racc[a]) : 0.f;
        sm_part[a * 128 + tid] = v;
    }
    __syncthreads();

    for (int a = wid; a < A; a += 4) {
        const float* row = sm_part + a * 128;
        float s = row[lane] + row[lane + 32] + row[lane + 64] + row[lane + 96];
        s += __shfl_xor_sync(0xffffffffu, s, 16);
        s += __shfl_xor_sync(0xffffffffu, s, 8);
        s += __shfl_xor_sync(0xffffffffu, s, 4);
        s += __shfl_xor_sync(0xffffffffu, s, 2);
        s += __shfl_xor_sync(0xffffffffu, s, 1);
        if (lane == 0) atomicAdd(&g_neg[aid0 + a], s);
    }

    if (tsplit == 0 && tid < A * 5) {
        int a = tid / 5, p = tid - a * 5;
        int xy = p + (p >= vl ? 1 : 0);
        const float4* pr = (const float4*)
            (g_proj + (size_t)(qbase + (xy * 6 + vl) * S + abase + a) * 256);
        const float4* ar = (const float4*)(sm_anch + a * 256);
        float d = 0.f;
        #pragma unroll 4
        for (int q = 0; q < 64; q++) {
            float4 x = pr[q], y = ar[q];
            d += x.x*y.x + x.y*y.y + x.z*y.z + x.w*y.w;
        }
        atomicAdd(&g_pos[aid0 + a], __expf(2.0f * d));
    }
}

// ---------------------------------------------------------------------------
__global__ void __launch_bounds__(256) finalize_kernel(float* __restrict__ out)
{
    int i = blockIdx.x * 256 + threadIdx.x;
    float loss = 0.f;
    if (i < N_ANCHORS) {
        float p = g_pos[i], n = g_neg[i];
        loss = -logf(p / (p + n));
    }
    loss += __shfl_xor_sync(0xffffffffu, loss, 16);
    loss += __shfl_xor_sync(0xffffffffu, loss, 8);
    loss += __shfl_xor_sync(0xffffffffu, loss, 4);
    loss += __shfl_xor_sync(0xffffffffu, loss, 2);
    loss += __shfl_xor_sync(0xffffffffu, loss, 1);
    __shared__ float wsum[8];
    int lane = threadIdx.x & 31, wid = threadIdx.x >> 5;
    if (lane == 0) wsum[wid] = loss;
    __syncthreads();
    if (wid == 0) {
        float s = (lane < 8) ? wsum[lane] : 0.f;
        s += __shfl_xor_sync(0xffffffffu, s, 4);
        s += __shfl_xor_sync(0xffffffffu, s, 2);
        s += __shfl_xor_sync(0xffffffffu, s, 1);
        if (lane == 0) atomicAdd(out, s * (1.0f / 1440.0f));
    }
}

// ---------------------------------------------------------------------------
extern "C" void kernel_launch(void* const* d_in, const int* in_sizes, int n_in,
                              void* d_out, int out_size)
{
    const float* E    = (const float*)d_in[0];
    const float* W1   = (const float*)d_in[1];
    const float* b1   = (const float*)d_in[2];
    const float* W2   = (const float*)d_in[3];
    const float* b2   = (const float*)d_in[4];
    const int*   idxp = (const int*)d_in[5];
    const int*   idxr = (const int*)d_in[6];
    const int*   negp = (const int*)d_in[7];
    const int*   negr = (const int*)d_in[8];
    float* out = (float*)d_out;
    (void)in_sizes; (void)n_in; (void)out_size;

    cudaFuncSetAttribute(proj_mma_kernel,
                         cudaFuncAttributeMaxDynamicSharedMemorySize, SM_BYTES);

    zero_kernel<<<6, 256>>>(out);
    prep_w_kernel<<<256, 256>>>(W1, W2);
    proj_mma_kernel<<<PROJ_BLOCKS, 512, SM_BYTES>>>(E, b1, b2,
                                                    idxp, idxr, negp, negr);
    loss_sims_kernel<25, 100, 50, 250, 2><<<96, 128>>>();
    loss_sims_kernel<20,  20, 10,  50, 1><<<12, 128>>>();
    finalize_kernel<<<6, 256>>>(out);
}

// round 5
// speedup vs baseline: 3.6835x; 1.5791x over previous
#include <cuda_runtime.h>
#include <cuda_fp16.h>
#include <math.h>
#include <stdint.h>

// ---------------------------------------------------------------------------
#define D        256
#define N_NODES  4000
#define LL       3
#define VV       2

#define Q_ROWS     8640
#define TOTAL_ROWS 10800
#define N_ANCHORS  1440

#define PROJ_BLOCKS 85      // ceil(10800 / 128)
#define ROWS_PB     128

__device__ unsigned int g_projh[(size_t)TOTAL_ROWS * 128];  // fp16 proj rows (5.5 MB)
__device__ unsigned int g_Wh[2][32768];   // fp16 W1/W2, row-major [n][k]
__device__ float g_pos[N_ANCHORS];
__device__ float g_neg[N_ANCHORS];

// ---------------------------------------------------------------------------
__device__ __forceinline__ uint32_t smem_u32(const void* p) {
    uint32_t a;
    asm("{ .reg .u64 t; cvta.to.shared.u64 t, %1; cvt.u32.u64 %0, t; }"
        : "=r"(a) : "l"(p));
    return a;
}
__device__ __forceinline__ void ldsm_x4(uint32_t* r, uint32_t addr) {
    asm volatile("ldmatrix.sync.aligned.m8n8.x4.shared.b16 {%0,%1,%2,%3}, [%4];"
                 : "=r"(r[0]), "=r"(r[1]), "=r"(r[2]), "=r"(r[3]) : "r"(addr));
}
__device__ __forceinline__ void ldsm_x2(uint32_t* r, uint32_t addr) {
    asm volatile("ldmatrix.sync.aligned.m8n8.x2.shared.b16 {%0,%1}, [%2];"
                 : "=r"(r[0]), "=r"(r[1]) : "r"(addr));
}
__device__ __forceinline__ void mma16816(float* c, const uint32_t* a,
                                         const uint32_t* b) {
    asm volatile("mma.sync.aligned.m16n8k16.row.col.f32.f16.f16.f32 "
                 "{%0,%1,%2,%3}, {%4,%5,%6,%7}, {%8,%9}, {%0,%1,%2,%3};"
                 : "+f"(c[0]), "+f"(c[1]), "+f"(c[2]), "+f"(c[3])
                 : "r"(a[0]), "r"(a[1]), "r"(a[2]), "r"(a[3]),
                   "r"(b[0]), "r"(b[1]));
}

// ---------------------------------------------------------------------------
// fp32 W -> fp16 row-major image; also zeroes accumulators & output
__global__ void prep_w_kernel(const float* __restrict__ W1,
                              const float* __restrict__ W2,
                              float* __restrict__ out)
{
    int i = blockIdx.x * blockDim.x + threadIdx.x;   // 0..65535
    if (i < N_ANCHORS) { g_pos[i] = 0.f; g_neg[i] = 0.f; }
    if (i == 0) out[0] = 0.f;
    int which = i >> 15;
    int r = i & 32767;                                // half2 index
    const float* W = which ? W2 : W1;
    __half2 h = __floats2half2_rn(W[r * 2], W[r * 2 + 1]);
    g_Wh[which][r] = *reinterpret_cast<unsigned int*>(&h);
}

// ---------------------------------------------------------------------------
__device__ __forceinline__ const float* map_src_row(
    int r, const float* __restrict__ E,
    const int* __restrict__ idxp, const int* __restrict__ idxr,
    const int* __restrict__ negp, const int* __restrict__ negr)
{
    if (r < Q_ROWS) {
        int t, local, S;
        if (r < 3600)      { t = 0; local = r;        S = 100; }
        else if (r < 7200) { t = 1; local = r - 3600; S = 100; }
        else if (r < 7920) { t = 2; local = r - 7200; S = 20;  }
        else               { t = 3; local = r - 7920; S = 20;  }
        int perxy = 6 * S;
        int xy  = local / perxy;
        int rem = local - xy * perxy;
        int node = (t < 2) ? idxp[t * 600 + rem] : idxr[(t - 2) * 120 + rem];
        int x = xy / LL, y = xy - x * LL;
        return E + ((size_t)(((t * VV + x) * LL + y) * N_NODES + node)) * D;
    } else {
        int rr = r - Q_ROWS;
        int t, local, K;
        if (rr < 900)       { t = 0; local = rr;        K = 50; }
        else if (rr < 1800) { t = 1; local = rr - 900;  K = 50; }
        else if (rr < 1980) { t = 2; local = rr - 1800; K = 10; }
        else                { t = 3; local = rr - 1980; K = 10; }
        int perO = 6 * K;
        int o   = local / perO;
        int vlk = local - o * perO;
        int vl  = vlk / K;
        int k   = vlk - vl * K;
        int off = (vl * 3 + o) * K + k;
        int node = (t < 2) ? negp[t * 900 + off] : negr[(t - 2) * 180 + off];
        int ot = o + (o >= t ? 1 : 0);
        int v = vl / LL, l = vl - v * LL;
        return E + ((size_t)(((ot * VV + v) * LL + l) * N_NODES + node)) * D;
    }
}

// ---------------------------------------------------------------------------
// Projection kernel (R4 structure): gather -> HMMA MLP -> normalize -> fp16 out
#define SMA   0
#define SMW   67584
#define CTRL  202752
#define SM_BYTES (CTRL + 3072 + 2048)

#define APITCH 264

__global__ void __launch_bounds__(512, 1)
proj_mma_kernel(const float* __restrict__ E,
                const float* __restrict__ b1, const float* __restrict__ b2,
                const int* __restrict__ idxp, const int* __restrict__ idxr,
                const int* __restrict__ negp, const int* __restrict__ negr)
{
    extern __shared__ char sm[];
    const uint32_t smb = smem_u32(sm);

    float* smb1 = (float*)(sm + CTRL);
    float* smb2 = (float*)(sm + CTRL + 1024);
    const float** srcp = (const float**)(sm + CTRL + 2048);
    float* ssbuf = (float*)(sm + CTRL + 3072);

    const int tid = threadIdx.x;
    const int l   = tid & 31;
    const int w   = tid >> 5;
    const int my  = w >> 2;
    const int cx  = w & 3;
    const int r0  = blockIdx.x * ROWS_PB;

    if (tid < 64)        ((float4*)smb1)[tid]      = ((const float4*)b1)[tid];
    else if (tid < 128)  ((float4*)smb2)[tid - 64] = ((const float4*)b2)[tid - 64];
    if (tid < ROWS_PB) {
        int r = r0 + tid;
        srcp[tid] = (r < TOTAL_ROWS)
                  ? map_src_row(r, E, idxp, idxr, negp, negr)
                  : (const float*)0;
    }

    for (int i = tid; i < 8192; i += 512) {
        int n = i >> 5, q = i & 31;
        *(float4*)(sm + SMW + (n * APITCH + q * 8) * 2) = ((const float4*)g_Wh[0])[i];
    }
    __syncthreads();

    for (int i = tid; i < ROWS_PB * 64; i += 512) {
        int m = i >> 6, q = i & 63;
        const float* s = srcp[m];
        float4 v = make_float4(0.f, 0.f, 0.f, 0.f);
        if (s) v = ((const float4*)s)[q];
        __half2 p0 = __floats2half2_rn(v.x, v.y);
        __half2 p1 = __floats2half2_rn(v.z, v.w);
        uint2 pk = make_uint2(*reinterpret_cast<unsigned int*>(&p0),
                              *reinterpret_cast<unsigned int*>(&p1));
        *(uint2*)(sm + SMA + (m * APITCH + q * 4) * 2) = pk;
    }
    __syncthreads();

    const uint32_t a_base = smb + SMA +
        ((my * 32 + ((l >> 3) & 1) * 8 + (l & 7)) * APITCH + (l >> 4) * 8) * 2;
    const uint32_t b_base = smb + SMW +
        ((cx * 64 + (l & 7)) * APITCH + ((l >> 3) & 1) * 8) * 2;

    float c[2][8][4];

    // layer 1
    #pragma unroll
    for (int mt = 0; mt < 2; mt++)
        #pragma unroll
        for (int nt = 0; nt < 8; nt++)
            #pragma unroll
            for (int j = 0; j < 4; j++) c[mt][nt][j] = 0.f;

    #pragma unroll 4
    for (int kk = 0; kk < 16; kk++) {
        uint32_t a[8];
        ldsm_x4(a,     a_base + kk * 32);
        ldsm_x4(a + 4, a_base + kk * 32 + 16 * APITCH * 2);
        #pragma unroll
        for (int nt = 0; nt < 8; nt++) {
            uint32_t b[2];
            ldsm_x2(b, b_base + kk * 32 + nt * 8 * APITCH * 2);
            mma16816(c[0][nt], a,     b);
            mma16816(c[1][nt], a + 4, b);
        }
    }
    __syncthreads();

    const int g  = l >> 2;
    const int q2 = (l & 3) * 2;
    #pragma unroll
    for (int mt = 0; mt < 2; mt++) {
        #pragma unroll
        for (int nt = 0; nt < 8; nt++) {
            int col = cx * 64 + nt * 8 + q2;
            float bx = smb1[col], by = smb1[col + 1];
            int rlo = my * 32 + mt * 16 + g;
            __half2 lo = __floats2half2_rn(fmaxf(c[mt][nt][0] + bx, 0.f),
                                           fmaxf(c[mt][nt][1] + by, 0.f));
            __half2 hi = __floats2half2_rn(fmaxf(c[mt][nt][2] + bx, 0.f),
                                           fmaxf(c[mt][nt][3] + by, 0.f));
            *(unsigned int*)(sm + SMA + (rlo * APITCH + col) * 2) =
                *reinterpret_cast<unsigned int*>(&lo);
            *(unsigned int*)(sm + SMA + ((rlo + 8) * APITCH + col) * 2) =
                *reinterpret_cast<unsigned int*>(&hi);
        }
    }
    for (int i = tid; i < 8192; i += 512) {
        int n = i >> 5, q = i & 31;
        *(float4*)(sm + SMW + (n * APITCH + q * 8) * 2) = ((const float4*)g_Wh[1])[i];
    }
    __syncthreads();

    // layer 2
    #pragma unroll
    for (int mt = 0; mt < 2; mt++)
        #pragma unroll
        for (int nt = 0; nt < 8; nt++)
            #pragma unroll
            for (int j = 0; j < 4; j++) c[mt][nt][j] = 0.f;

    #pragma unroll 4
    for (int kk = 0; kk < 16; kk++) {
        uint32_t a[8];
        ldsm_x4(a,     a_base + kk * 32);
        ldsm_x4(a + 4, a_base + kk * 32 + 16 * APITCH * 2);
        #pragma unroll
        for (int nt = 0; nt < 8; nt++) {
            uint32_t b[2];
            ldsm_x2(b, b_base + kk * 32 + nt * 8 * APITCH * 2);
            mma16816(c[0][nt], a,     b);
            mma16816(c[1][nt], a + 4, b);
        }
    }

    // epilogue: bias, row L2-norm, fp16 store
    float ss[4] = {0.f, 0.f, 0.f, 0.f};
    #pragma unroll
    for (int mt = 0; mt < 2; mt++) {
        #pragma unroll
        for (int nt = 0; nt < 8; nt++) {
            int col = cx * 64 + nt * 8 + q2;
            float bx = smb2[col], by = smb2[col + 1];
            float z0 = c[mt][nt][0] + bx, z1 = c[mt][nt][1] + by;
            float z2 = c[mt][nt][2] + bx, z3 = c[mt][nt][3] + by;
            ss[mt * 2]     += z0 * z0 + z1 * z1;
            ss[mt * 2 + 1] += z2 * z2 + z3 * z3;
        }
    }
    #pragma unroll
    for (int j = 0; j < 4; j++) {
        ss[j] += __shfl_xor_sync(0xffffffffu, ss[j], 1);
        ss[j] += __shfl_xor_sync(0xffffffffu, ss[j], 2);
    }
    if ((l & 3) == 0) {
        #pragma unroll
        for (int j = 0; j < 4; j++) {
            int row = my * 32 + (j >> 1) * 16 + (j & 1) * 8 + g;
            ssbuf[row * 4 + cx] = ss[j];
        }
    }
    __syncthreads();

    float inv[4];
    #pragma unroll
    for (int j = 0; j < 4; j++) {
        int row = my * 32 + (j >> 1) * 16 + (j & 1) * 8 + g;
        float t = ssbuf[row * 4 + 0] + ssbuf[row * 4 + 1]
                + ssbuf[row * 4 + 2] + ssbuf[row * 4 + 3];
        inv[j] = 1.0f / fmaxf(sqrtf(t), 1e-12f);
    }

    #pragma unroll
    for (int mt = 0; mt < 2; mt++) {
        #pragma unroll
        for (int nt = 0; nt < 8; nt++) {
            int col = cx * 64 + nt * 8 + q2;
            float bx = smb2[col], by = smb2[col + 1];
            int rlo = r0 + my * 32 + mt * 16 + g;
            int rhi = rlo + 8;
            int ci = (col >> 1);
            if (rlo < TOTAL_ROWS) {
                __half2 h = __floats2half2_rn((c[mt][nt][0] + bx) * inv[mt * 2],
                                              (c[mt][nt][1] + by) * inv[mt * 2]);
                g_projh[(size_t)rlo * 128 + ci] = *reinterpret_cast<unsigned int*>(&h);
            }
            if (rhi < TOTAL_ROWS) {
                __half2 h = __floats2half2_rn((c[mt][nt][2] + bx) * inv[mt * 2 + 1],
                                              (c[mt][nt][3] + by) * inv[mt * 2 + 1]);
                g_projh[(size_t)rhi * 128 + ci] = *reinterpret_cast<unsigned int*>(&h);
            }
        }
    }
}

// ---------------------------------------------------------------------------
// Loss via HMMA sim-GEMM. Block = (type, vl, chunk of 256 targets).
//   blocks [0,36): big types  (S=100, K=50, 3 chunks each)
//   blocks [36,48): small types (S=20, K=10, 1 chunk)
// A tile: 128 padded anchors (fp16). B tile: 256 target rows (fp16).
#define LSMA 0
#define LSMB 67584
#define LTRG 202752
#define LSM_BYTES (LTRG + 1024 + 64)

__global__ void __launch_bounds__(512, 1)
loss_mma_kernel()
{
    extern __shared__ char sm[];
    const uint32_t smb = smem_u32(sm);
    int* targ = (int*)(sm + LTRG);

    const int tid = threadIdx.x;
    const int l   = tid & 31;
    const int w   = tid >> 5;
    const int my  = w >> 2;
    const int cx  = w & 3;
    const int b   = blockIdx.x;

    int S, K, vl, chunk, qbase, pbase, aid0;
    if (b < 36) {
        int t = b / 18, rem = b % 18;
        vl = rem / 3; chunk = rem % 3;
        S = 100; K = 50;
        qbase = t * 3600; pbase = t * 900;
        aid0  = t * 600 + vl * 100;
    } else {
        int bs = b - 36;
        int t2 = bs / 6;
        vl = bs % 6; chunk = 0;
        S = 20; K = 10;
        qbase = 7200 + t2 * 720; pbase = 1800 + t2 * 180;
        aid0  = 1200 + t2 * 120 + vl * 20;
    }
    const int NTARG = 6 * S + 3 * K;
    const int diag_base = qbase + vl * 7 * S;

    // target row table
    if (tid < 256) {
        int n = chunk * 256 + tid;
        int row = 0;
        if (n < 6 * S) {
            int xy = n / S, ts = n - xy * S;
            row = qbase + (xy * 6 + vl) * S + ts;
        } else if (n < NTARG) {
            int cc = n - 6 * S;
            int o = cc / K, k = cc - o * K;
            row = Q_ROWS + pbase + (o * 6 + vl) * K + k;
        }
        targ[tid] = row;
    }
    __syncthreads();

    // load A (anchors) and B (targets) fp16 tiles
    for (int i = tid; i < 128 * 32; i += 512) {
        int r = i >> 5, q = i & 31;
        int arow = diag_base + (r < S ? r : 0);
        *(float4*)(sm + LSMA + (r * APITCH + q * 8) * 2) =
            ((const float4*)g_projh)[(size_t)arow * 32 + q];
    }
    for (int i = tid; i < 256 * 32; i += 512) {
        int r = i >> 5, q = i & 31;
        *(float4*)(sm + LSMB + (r * APITCH + q * 8) * 2) =
            ((const float4*)g_projh)[(size_t)targ[r] * 32 + q];
    }
    __syncthreads();

    const uint32_t a_base = smb + LSMA +
        ((my * 32 + ((l >> 3) & 1) * 8 + (l & 7)) * APITCH + (l >> 4) * 8) * 2;
    const uint32_t b_base = smb + LSMB +
        ((cx * 64 + (l & 7)) * APITCH + ((l >> 3) & 1) * 8) * 2;

    float c[2][8][4];
    #pragma unroll
    for (int mt = 0; mt < 2; mt++)
        #pragma unroll
        for (int nt = 0; nt < 8; nt++)
            #pragma unroll
            for (int j = 0; j < 4; j++) c[mt][nt][j] = 0.f;

    #pragma unroll 4
    for (int kk = 0; kk < 16; kk++) {
        uint32_t a[8];
        ldsm_x4(a,     a_base + kk * 32);
        ldsm_x4(a + 4, a_base + kk * 32 + 16 * APITCH * 2);
        #pragma unroll
        for (int nt = 0; nt < 8; nt++) {
            uint32_t bb[2];
            ldsm_x2(bb, b_base + kk * 32 + nt * 8 * APITCH * 2);
            mma16816(c[0][nt], a,     bb);
            mma16816(c[1][nt], a + 4, bb);
        }
    }

    // epilogue: classify + exp + accumulate
    const int g  = l >> 2;
    const int q2 = (l & 3) * 2;
    float pacc[4] = {0.f, 0.f, 0.f, 0.f};
    float nacc[4] = {0.f, 0.f, 0.f, 0.f};

    #pragma unroll
    for (int mt = 0; mt < 2; mt++) {
        #pragma unroll
        for (int jh = 0; jh < 2; jh++) {
            int rowl = my * 32 + mt * 16 + jh * 8 + g;
            int slot = mt * 2 + jh;
            if (rowl < S) {
                #pragma unroll
                for (int nt = 0; nt < 8; nt++) {
                    #pragma unroll
                    for (int jl = 0; jl < 2; jl++) {
                        float v = c[mt][nt][jh * 2 + jl];
                        int n = chunk * 256 + cx * 64 + nt * 8 + q2 + jl;
                        if (n < 6 * S) {
                            int xy = n / S, ts = n - xy * S;
                            if (xy == vl) {
                                if (ts != rowl) nacc[slot] += __expf(2.0f * v);
                            } else if (ts == rowl) {
                                pacc[slot] += __expf(2.0f * v);
                            }
                        } else if (n < NTARG) {
                            nacc[slot] += __expf(2.0f * v);
                        }
                    }
                }
            }
        }
    }

    #pragma unroll
    for (int s = 0; s < 4; s++) {
        pacc[s] += __shfl_xor_sync(0xffffffffu, pacc[s], 1);
        pacc[s] += __shfl_xor_sync(0xffffffffu, pacc[s], 2);
        nacc[s] += __shfl_xor_sync(0xffffffffu, nacc[s], 1);
        nacc[s] += __shfl_xor_sync(0xffffffffu, nacc[s], 2);
    }
    if ((l & 3) == 0) {
        #pragma unroll
        for (int s = 0; s < 4; s++) {
            int rowl = my * 32 + (s >> 1) * 16 + (s & 1) * 8 + g;
            if (rowl < S) {
                if (pacc[s] != 0.f) atomicAdd(&g_pos[aid0 + rowl], pacc[s]);
                if (nacc[s] != 0.f) atomicAdd(&g_neg[aid0 + rowl], nacc[s]);
            }
        }
    }
}

// ---------------------------------------------------------------------------
__global__ void __launch_bounds__(256) finalize_kernel(float* __restrict__ out)
{
    int i = blockIdx.x * 256 + threadIdx.x;
    float loss = 0.f;
    if (i < N_ANCHORS) {
        float p = g_pos[i], n = g_neg[i];
        loss = -logf(p / (p + n));
    }
    loss += __shfl_xor_sync(0xffffffffu, loss, 16);
    loss += __shfl_xor_sync(0xffffffffu, loss, 8);
    loss += __shfl_xor_sync(0xffffffffu, loss, 4);
    loss += __shfl_xor_sync(0xffffffffu, loss, 2);
    loss += __shfl_xor_sync(0xffffffffu, loss, 1);
    __shared__ float wsum[8];
    int lane = threadIdx.x & 31, wid = threadIdx.x >> 5;
    if (lane == 0) wsum[wid] = loss;
    __syncthreads();
    if (wid == 0) {
        float s = (lane < 8) ? wsum[lane] : 0.f;
        s += __shfl_xor_sync(0xffffffffu, s, 4);
        s += __shfl_xor_sync(0xffffffffu, s, 2);
        s += __shfl_xor_sync(0xffffffffu, s, 1);
        if (lane == 0) atomicAdd(out, s * (1.0f / 1440.0f));
    }
}

// ---------------------------------------------------------------------------
extern "C" void kernel_launch(void* const* d_in, const int* in_sizes, int n_in,
                              void* d_out, int out_size)
{
    const float* E    = (const float*)d_in[0];
    const float* W1   = (const float*)d_in[1];
    const float* b1   = (const float*)d_in[2];
    const float* W2   = (const float*)d_in[3];
    const float* b2   = (const float*)d_in[4];
    const int*   idxp = (const int*)d_in[5];
    const int*   idxr = (const int*)d_in[6];
    const int*   negp = (const int*)d_in[7];
    const int*   negr = (const int*)d_in[8];
    float* out = (float*)d_out;
    (void)in_sizes; (void)n_in; (void)out_size;

    cudaFuncSetAttribute(proj_mma_kernel,
                         cudaFuncAttributeMaxDynamicSharedMemorySize, SM_BYTES);
    cudaFuncSetAttribute(loss_mma_kernel,
                         cudaFuncAttributeMaxDynamicSharedMemorySize, LSM_BYTES);

    prep_w_kernel<<<256, 256>>>(W1, W2, out);
    proj_mma_kernel<<<PROJ_BLOCKS, 512, SM_BYTES>>>(E, b1, b2,
                                                    idxp, idxr, negp, negr);
    loss_mma_kernel<<<48, 512, LSM_BYTES>>>();
    finalize_kernel<<<6, 256>>>(out);
}

// round 6
// speedup vs baseline: 3.8238x; 1.0381x over previous
#include <cuda_runtime.h>
#include <cuda_fp16.h>
#include <math.h>
#include <stdint.h>

// ---------------------------------------------------------------------------
#define D        256
#define N_NODES  4000
#define LL       3
#define VV       2

#define Q_ROWS     8640
#define TOTAL_ROWS 10800
#define N_ANCHORS  1440

#define PROJ_BLOCKS 85      // ceil(10800 / 128)
#define ROWS_PB     128

__device__ unsigned int g_projh[(size_t)TOTAL_ROWS * 128];  // fp16 proj rows
__device__ float g_pos[N_ANCHORS];
__device__ float g_neg[N_ANCHORS];
__device__ unsigned int g_ctr;

// ---------------------------------------------------------------------------
__device__ __forceinline__ uint32_t smem_u32(const void* p) {
    uint32_t a;
    asm("{ .reg .u64 t; cvta.to.shared.u64 t, %1; cvt.u32.u64 %0, t; }"
        : "=r"(a) : "l"(p));
    return a;
}
__device__ __forceinline__ void ldsm_x4(uint32_t* r, uint32_t addr) {
    asm volatile("ldmatrix.sync.aligned.m8n8.x4.shared.b16 {%0,%1,%2,%3}, [%4];"
                 : "=r"(r[0]), "=r"(r[1]), "=r"(r[2]), "=r"(r[3]) : "r"(addr));
}
__device__ __forceinline__ void ldsm_x2(uint32_t* r, uint32_t addr) {
    asm volatile("ldmatrix.sync.aligned.m8n8.x2.shared.b16 {%0,%1}, [%2];"
                 : "=r"(r[0]), "=r"(r[1]) : "r"(addr));
}
__device__ __forceinline__ void mma16816(float* c, const uint32_t* a,
                                         const uint32_t* b) {
    asm volatile("mma.sync.aligned.m16n8k16.row.col.f32.f16.f16.f32 "
                 "{%0,%1,%2,%3}, {%4,%5,%6,%7}, {%8,%9}, {%0,%1,%2,%3};"
                 : "+f"(c[0]), "+f"(c[1]), "+f"(c[2]), "+f"(c[3])
                 : "r"(a[0]), "r"(a[1]), "r"(a[2]), "r"(a[3]),
                   "r"(b[0]), "r"(b[1]));
}

// ---------------------------------------------------------------------------
__device__ __forceinline__ const float* map_src_row(
    int r, const float* __restrict__ E,
    const int* __restrict__ idxp, const int* __restrict__ idxr,
    const int* __restrict__ negp, const int* __restrict__ negr)
{
    if (r < Q_ROWS) {
        int t, local, S;
        if (r < 3600)      { t = 0; local = r;        S = 100; }
        else if (r < 7200) { t = 1; local = r - 3600; S = 100; }
        else if (r < 7920) { t = 2; local = r - 7200; S = 20;  }
        else               { t = 3; local = r - 7920; S = 20;  }
        int perxy = 6 * S;
        int xy  = local / perxy;
        int rem = local - xy * perxy;
        int node = (t < 2) ? idxp[t * 600 + rem] : idxr[(t - 2) * 120 + rem];
        int x = xy / LL, y = xy - x * LL;
        return E + ((size_t)(((t * VV + x) * LL + y) * N_NODES + node)) * D;
    } else {
        int rr = r - Q_ROWS;
        int t, local, K;
        if (rr < 900)       { t = 0; local = rr;        K = 50; }
        else if (rr < 1800) { t = 1; local = rr - 900;  K = 50; }
        else if (rr < 1980) { t = 2; local = rr - 1800; K = 10; }
        else                { t = 3; local = rr - 1980; K = 10; }
        int perO = 6 * K;
        int o   = local / perO;
        int vlk = local - o * perO;
        int vl  = vlk / K;
        int k   = vlk - vl * K;
        int off = (vl * 3 + o) * K + k;
        int node = (t < 2) ? negp[t * 900 + off] : negr[(t - 2) * 180 + off];
        int ot = o + (o >= t ? 1 : 0);
        int v = vl / LL, l = vl - v * LL;
        return E + ((size_t)(((ot * VV + v) * LL + l) * N_NODES + node)) * D;
    }
}

// ---------------------------------------------------------------------------
// Projection: gather + inline W fp32->fp16 + HMMA MLP + normalize -> fp16 out.
// Also zeroes the loss accumulators (block 0) — kernel boundary orders it.
#define SMA   0
#define SMW   67584
#define CTRL  202752
#define SM_BYTES (CTRL + 3072 + 2048)

#define APITCH 264

__global__ void __launch_bounds__(512, 1)
proj_mma_kernel(const float* __restrict__ E,
                const float* __restrict__ W1, const float* __restrict__ b1,
                const float* __restrict__ W2, const float* __restrict__ b2,
                const int* __restrict__ idxp, const int* __restrict__ idxr,
                const int* __restrict__ negp, const int* __restrict__ negr)
{
    extern __shared__ char sm[];
    const uint32_t smb = smem_u32(sm);

    float* smb1 = (float*)(sm + CTRL);
    float* smb2 = (float*)(sm + CTRL + 1024);
    const float** srcp = (const float**)(sm + CTRL + 2048);
    float* ssbuf = (float*)(sm + CTRL + 3072);

    const int tid = threadIdx.x;
    const int l   = tid & 31;
    const int w   = tid >> 5;
    const int my  = w >> 2;
    const int cx  = w & 3;
    const int r0  = blockIdx.x * ROWS_PB;

    if (blockIdx.x == 0) {
        for (int i = tid; i < N_ANCHORS; i += 512) { g_pos[i] = 0.f; g_neg[i] = 0.f; }
        if (tid == 0) g_ctr = 0u;
    }

    if (tid < 64)        ((float4*)smb1)[tid]      = ((const float4*)b1)[tid];
    else if (tid < 128)  ((float4*)smb2)[tid - 64] = ((const float4*)b2)[tid - 64];
    if (tid < ROWS_PB) {
        int r = r0 + tid;
        srcp[tid] = (r < TOTAL_ROWS)
                  ? map_src_row(r, E, idxp, idxr, negp, negr)
                  : (const float*)0;
    }

    // W1 fp32 -> fp16 smem tile (row n, 64 float4 per row)
    for (int i = tid; i < 16384; i += 512) {
        int n = i >> 6, q = i & 63;
        float4 v = ((const float4*)W1)[i];
        __half2 p0 = __floats2half2_rn(v.x, v.y);
        __half2 p1 = __floats2half2_rn(v.z, v.w);
        uint2 pk = make_uint2(*reinterpret_cast<unsigned int*>(&p0),
                              *reinterpret_cast<unsigned int*>(&p1));
        *(uint2*)(sm + SMW + (n * APITCH + q * 4) * 2) = pk;
    }
    __syncthreads();

    // gather X -> fp16 A tile
    for (int i = tid; i < ROWS_PB * 64; i += 512) {
        int m = i >> 6, q = i & 63;
        const float* s = srcp[m];
        float4 v = make_float4(0.f, 0.f, 0.f, 0.f);
        if (s) v = ((const float4*)s)[q];
        __half2 p0 = __floats2half2_rn(v.x, v.y);
        __half2 p1 = __floats2half2_rn(v.z, v.w);
        uint2 pk = make_uint2(*reinterpret_cast<unsigned int*>(&p0),
                              *reinterpret_cast<unsigned int*>(&p1));
        *(uint2*)(sm + SMA + (m * APITCH + q * 4) * 2) = pk;
    }
    __syncthreads();

    const uint32_t a_base = smb + SMA +
        ((my * 32 + ((l >> 3) & 1) * 8 + (l & 7)) * APITCH + (l >> 4) * 8) * 2;
    const uint32_t b_base = smb + SMW +
        ((cx * 64 + (l & 7)) * APITCH + ((l >> 3) & 1) * 8) * 2;

    float c[2][8][4];

    // layer 1
    #pragma unroll
    for (int mt = 0; mt < 2; mt++)
        #pragma unroll
        for (int nt = 0; nt < 8; nt++)
            #pragma unroll
            for (int j = 0; j < 4; j++) c[mt][nt][j] = 0.f;

    #pragma unroll 4
    for (int kk = 0; kk < 16; kk++) {
        uint32_t a[8];
        ldsm_x4(a,     a_base + kk * 32);
        ldsm_x4(a + 4, a_base + kk * 32 + 16 * APITCH * 2);
        #pragma unroll
        for (int nt = 0; nt < 8; nt++) {
            uint32_t b[2];
            ldsm_x2(b, b_base + kk * 32 + nt * 8 * APITCH * 2);
            mma16816(c[0][nt], a,     b);
            mma16816(c[1][nt], a + 4, b);
        }
    }
    __syncthreads();

    const int g  = l >> 2;
    const int q2 = (l & 3) * 2;
    #pragma unroll
    for (int mt = 0; mt < 2; mt++) {
        #pragma unroll
        for (int nt = 0; nt < 8; nt++) {
            int col = cx * 64 + nt * 8 + q2;
            float bx = smb1[col], by = smb1[col + 1];
            int rlo = my * 32 + mt * 16 + g;
            __half2 lo = __floats2half2_rn(fmaxf(c[mt][nt][0] + bx, 0.f),
                                           fmaxf(c[mt][nt][1] + by, 0.f));
            __half2 hi = __floats2half2_rn(fmaxf(c[mt][nt][2] + bx, 0.f),
                                           fmaxf(c[mt][nt][3] + by, 0.f));
            *(unsigned int*)(sm + SMA + (rlo * APITCH + col) * 2) =
                *reinterpret_cast<unsigned int*>(&lo);
            *(unsigned int*)(sm + SMA + ((rlo + 8) * APITCH + col) * 2) =
                *reinterpret_cast<unsigned int*>(&hi);
        }
    }
    // W2 fp32 -> fp16 smem tile
    for (int i = tid; i < 16384; i += 512) {
        int n = i >> 6, q = i & 63;
        float4 v = ((const float4*)W2)[i];
        __half2 p0 = __floats2half2_rn(v.x, v.y);
        __half2 p1 = __floats2half2_rn(v.z, v.w);
        uint2 pk = make_uint2(*reinterpret_cast<unsigned int*>(&p0),
                              *reinterpret_cast<unsigned int*>(&p1));
        *(uint2*)(sm + SMW + (n * APITCH + q * 4) * 2) = pk;
    }
    __syncthreads();

    // layer 2
    #pragma unroll
    for (int mt = 0; mt < 2; mt++)
        #pragma unroll
        for (int nt = 0; nt < 8; nt++)
            #pragma unroll
            for (int j = 0; j < 4; j++) c[mt][nt][j] = 0.f;

    #pragma unroll 4
    for (int kk = 0; kk < 16; kk++) {
        uint32_t a[8];
        ldsm_x4(a,     a_base + kk * 32);
        ldsm_x4(a + 4, a_base + kk * 32 + 16 * APITCH * 2);
        #pragma unroll
        for (int nt = 0; nt < 8; nt++) {
            uint32_t b[2];
            ldsm_x2(b, b_base + kk * 32 + nt * 8 * APITCH * 2);
            mma16816(c[0][nt], a,     b);
            mma16816(c[1][nt], a + 4, b);
        }
    }

    // epilogue: bias, row L2-norm, fp16 store
    float ss[4] = {0.f, 0.f, 0.f, 0.f};
    #pragma unroll
    for (int mt = 0; mt < 2; mt++) {
        #pragma unroll
        for (int nt = 0; nt < 8; nt++) {
            int col = cx * 64 + nt * 8 + q2;
            float bx = smb2[col], by = smb2[col + 1];
            float z0 = c[mt][nt][0] + bx, z1 = c[mt][nt][1] + by;
            float z2 = c[mt][nt][2] + bx, z3 = c[mt][nt][3] + by;
            ss[mt * 2]     += z0 * z0 + z1 * z1;
            ss[mt * 2 + 1] += z2 * z2 + z3 * z3;
        }
    }
    #pragma unroll
    for (int j = 0; j < 4; j++) {
        ss[j] += __shfl_xor_sync(0xffffffffu, ss[j], 1);
        ss[j] += __shfl_xor_sync(0xffffffffu, ss[j], 2);
    }
    if ((l & 3) == 0) {
        #pragma unroll
        for (int j = 0; j < 4; j++) {
            int row = my * 32 + (j >> 1) * 16 + (j & 1) * 8 + g;
            ssbuf[row * 4 + cx] = ss[j];
        }
    }
    __syncthreads();

    float inv[4];
    #pragma unroll
    for (int j = 0; j < 4; j++) {
        int row = my * 32 + (j >> 1) * 16 + (j & 1) * 8 + g;
        float t = ssbuf[row * 4 + 0] + ssbuf[row * 4 + 1]
                + ssbuf[row * 4 + 2] + ssbuf[row * 4 + 3];
        inv[j] = 1.0f / fmaxf(sqrtf(t), 1e-12f);
    }

    #pragma unroll
    for (int mt = 0; mt < 2; mt++) {
        #pragma unroll
        for (int nt = 0; nt < 8; nt++) {
            int col = cx * 64 + nt * 8 + q2;
            float bx = smb2[col], by = smb2[col + 1];
            int rlo = r0 + my * 32 + mt * 16 + g;
            int rhi = rlo + 8;
            int ci = (col >> 1);
            if (rlo < TOTAL_ROWS) {
                __half2 h = __floats2half2_rn((c[mt][nt][0] + bx) * inv[mt * 2],
                                              (c[mt][nt][1] + by) * inv[mt * 2]);
                g_projh[(size_t)rlo * 128 + ci] = *reinterpret_cast<unsigned int*>(&h);
            }
            if (rhi < TOTAL_ROWS) {
                __half2 h = __floats2half2_rn((c[mt][nt][2] + bx) * inv[mt * 2 + 1],
                                              (c[mt][nt][3] + by) * inv[mt * 2 + 1]);
                g_projh[(size_t)rhi * 128 + ci] = *reinterpret_cast<unsigned int*>(&h);
            }
        }
    }
}

// ---------------------------------------------------------------------------
// Loss via HMMA sim-GEMM + fused finalize. 84 blocks x 256 threads.
//   blocks [0,72): big types: t = b/36, vl, mtile(2), chunk(3)
//   blocks [72,84): small types
// A tile: 64 anchors. B tile: 256 targets. M64 x N256 x K256 per block.
#define LSMA 0
#define LSMB 34816
#define LTRG 169984
#define LSM_BYTES (LTRG + 1024 + 128)

__global__ void __launch_bounds__(256, 1)
loss_mma_kernel(float* __restrict__ out)
{
    extern __shared__ char sm[];
    const uint32_t smb = smem_u32(sm);
    int* targ = (int*)(sm + LTRG);

    const int tid = threadIdx.x;
    const int l   = tid & 31;
    const int w   = tid >> 5;
    const int my  = w >> 2;          // 0..1
    const int cx  = w & 3;           // 0..3
    const int b   = blockIdx.x;

    int S, K, vl, chunk, mtile, qbase, pbase, aid0;
    if (b < 72) {
        int t = b / 36, rem = b % 36;
        vl = rem / 6;
        int r2 = rem % 6;
        mtile = r2 / 3; chunk = r2 % 3;
        S = 100; K = 50;
        qbase = t * 3600; pbase = t * 900;
        aid0  = t * 600 + vl * 100;
    } else {
        int bs = b - 72;
        int t2 = bs / 6;
        vl = bs % 6; chunk = 0; mtile = 0;
        S = 20; K = 10;
        qbase = 7200 + t2 * 720; pbase = 1800 + t2 * 180;
        aid0  = 1200 + t2 * 120 + vl * 20;
    }
    const int NTARG = 6 * S + 3 * K;
    const int diag_base = qbase + vl * 7 * S;
    const int mrow0 = mtile * 64;

    if (tid < 256) {
        int n = chunk * 256 + tid;
        int row = 0;
        if (n < 6 * S) {
            int xy = n / S, ts = n - xy * S;
            row = qbase + (xy * 6 + vl) * S + ts;
        } else if (n < NTARG) {
            int cc = n - 6 * S;
            int o = cc / K, k = cc - o * K;
            row = Q_ROWS + pbase + (o * 6 + vl) * K + k;
        }
        targ[tid] = row;
    }
    __syncthreads();

    // A (64 anchors) and B (256 targets) fp16 tiles
    for (int i = tid; i < 64 * 32; i += 256) {
        int r = i >> 5, q = i & 31;
        int gr = mrow0 + r;
        int arow = diag_base + (gr < S ? gr : 0);
        *(float4*)(sm + LSMA + (r * APITCH + q * 8) * 2) =
            ((const float4*)g_projh)[(size_t)arow * 32 + q];
    }
    for (int i = tid; i < 256 * 32; i += 256) {
        int r = i >> 5, q = i & 31;
        *(float4*)(sm + LSMB + (r * APITCH + q * 8) * 2) =
            ((const float4*)g_projh)[(size_t)targ[r] * 32 + q];
    }
    __syncthreads();

    const uint32_t a_base = smb + LSMA +
        ((my * 32 + ((l >> 3) & 1) * 8 + (l & 7)) * APITCH + (l >> 4) * 8) * 2;
    const uint32_t b_base = smb + LSMB +
        ((cx * 64 + (l & 7)) * APITCH + ((l >> 3) & 1) * 8) * 2;

    float c[2][8][4];
    #pragma unroll
    for (int mt = 0; mt < 2; mt++)
        #pragma unroll
        for (int nt = 0; nt < 8; nt++)
            #pragma unroll
            for (int j = 0; j < 4; j++) c[mt][nt][j] = 0.f;

    #pragma unroll 4
    for (int kk = 0; kk < 16; kk++) {
        uint32_t a[8];
        ldsm_x4(a,     a_base + kk * 32);
        ldsm_x4(a + 4, a_base + kk * 32 + 16 * APITCH * 2);
        #pragma unroll
        for (int nt = 0; nt < 8; nt++) {
            uint32_t bb[2];
            ldsm_x2(bb, b_base + kk * 32 + nt * 8 * APITCH * 2);
            mma16816(c[0][nt], a,     bb);
            mma16816(c[1][nt], a + 4, bb);
        }
    }

    const int g  = l >> 2;
    const int q2 = (l & 3) * 2;
    float pacc[4] = {0.f, 0.f, 0.f, 0.f};
    float nacc[4] = {0.f, 0.f, 0.f, 0.f};

    #pragma unroll
    for (int mt = 0; mt < 2; mt++) {
        #pragma unroll
        for (int jh = 0; jh < 2; jh++) {
            int rowg = mrow0 + my * 32 + mt * 16 + jh * 8 + g;
            int slot = mt * 2 + jh;
            if (rowg < S) {
                #pragma unroll
                for (int nt = 0; nt < 8; nt++) {
                    #pragma unroll
                    for (int jl = 0; jl < 2; jl++) {
                        float v = c[mt][nt][jh * 2 + jl];
                        int n = chunk * 256 + cx * 64 + nt * 8 + q2 + jl;
                        if (n < 6 * S) {
                            int xy = n / S, ts = n - xy * S;
                            if (xy == vl) {
                                if (ts != rowg) nacc[slot] += __expf(2.0f * v);
                            } else if (ts == rowg) {
                                pacc[slot] += __expf(2.0f * v);
                            }
                        } else if (n < NTARG) {
                            nacc[slot] += __expf(2.0f * v);
                        }
                    }
                }
            }
        }
    }

    #pragma unroll
    for (int s = 0; s < 4; s++) {
        pacc[s] += __shfl_xor_sync(0xffffffffu, pacc[s], 1);
        pacc[s] += __shfl_xor_sync(0xffffffffu, pacc[s], 2);
        nacc[s] += __shfl_xor_sync(0xffffffffu, nacc[s], 1);
        nacc[s] += __shfl_xor_sync(0xffffffffu, nacc[s], 2);
    }
    if ((l & 3) == 0) {
        #pragma unroll
        for (int s = 0; s < 4; s++) {
            int rowg = mrow0 + my * 32 + (s >> 1) * 16 + (s & 1) * 8 + g;
            if (rowg < S) {
                if (pacc[s] != 0.f) atomicAdd(&g_pos[aid0 + rowg], pacc[s]);
                if (nacc[s] != 0.f) atomicAdd(&g_neg[aid0 + rowg], nacc[s]);
            }
        }
    }

    // ---- fused finalize: last block computes the mean loss ----
    __shared__ unsigned int is_last;
    __threadfence();
    __syncthreads();
    if (tid == 0)
        is_last = (atomicAdd(&g_ctr, 1u) == (unsigned)(gridDim.x - 1));
    __syncthreads();
    if (is_last) {
        float loc = 0.f;
        for (int i = tid; i < N_ANCHORS; i += 256) {
            float p = g_pos[i], n = g_neg[i];
            loc += -logf(p / (p + n));
        }
        loc += __shfl_xor_sync(0xffffffffu, loc, 16);
        loc += __shfl_xor_sync(0xffffffffu, loc, 8);
        loc += __shfl_xor_sync(0xffffffffu, loc, 4);
        loc += __shfl_xor_sync(0xffffffffu, loc, 2);
        loc += __shfl_xor_sync(0xffffffffu, loc, 1);
        float* red = (float*)(sm + LTRG + 1024);
        if (l == 0) red[w] = loc;
        __syncthreads();
        if (w == 0) {
            float s = (l < 8) ? red[l] : 0.f;
            s += __shfl_xor_sync(0xffffffffu, s, 4);
            s += __shfl_xor_sync(0xffffffffu, s, 2);
            s += __shfl_xor_sync(0xffffffffu, s, 1);
            if (l == 0) out[0] = s * (1.0f / 1440.0f);
        }
    }
}

// ---------------------------------------------------------------------------
extern "C" void kernel_launch(void* const* d_in, const int* in_sizes, int n_in,
                              void* d_out, int out_size)
{
    const float* E    = (const float*)d_in[0];
    const float* W1   = (const float*)d_in[1];
    const float* b1   = (const float*)d_in[2];
    const float* W2   = (const float*)d_in[3];
    const float* b2   = (const float*)d_in[4];
    const int*   idxp = (const int*)d_in[5];
    const int*   idxr = (const int*)d_in[6];
    const int*   negp = (const int*)d_in[7];
    const int*   negr = (const int*)d_in[8];
    float* out = (float*)d_out;
    (void)in_sizes; (void)n_in; (void)out_size;

    cudaFuncSetAttribute(proj_mma_kernel,
                         cudaFuncAttributeMaxDynamicSharedMemorySize, SM_BYTES);
    cudaFuncSetAttribute(loss_mma_kernel,
                         cudaFuncAttributeMaxDynamicSharedMemorySize, LSM_BYTES);

    proj_mma_kernel<<<PROJ_BLOCKS, 512, SM_BYTES>>>(E, W1, b1, W2, b2,
                                                    idxp, idxr, negp, negr);
    loss_mma_kernel<<<84, 256, LSM_BYTES>>>(out);
}

// round 7
// speedup vs baseline: 4.9568x; 1.2963x over previous
#include <cuda_runtime.h>
#include <cuda_fp16.h>
#include <math.h>
#include <stdint.h>

// ---------------------------------------------------------------------------
#define D        256
#define N_NODES  4000
#define LL       3
#define VV       2

#define Q_ROWS     8640
#define TOTAL_ROWS 10800
#define N_ANCHORS  1440

#define PROJ_BLOCKS 85      // ceil(10800 / 128)
#define ROWS_PB     128

__device__ unsigned int g_projh[(size_t)TOTAL_ROWS * 128];  // fp16 proj rows
__device__ float g_pos[N_ANCHORS];
__device__ float g_neg[N_ANCHORS];
__device__ unsigned int g_ctr;

// ---------------------------------------------------------------------------
__device__ __forceinline__ uint32_t smem_u32(const void* p) {
    uint32_t a;
    asm("{ .reg .u64 t; cvta.to.shared.u64 t, %1; cvt.u32.u64 %0, t; }"
        : "=r"(a) : "l"(p));
    return a;
}
__device__ __forceinline__ void ldsm_x4(uint32_t* r, uint32_t addr) {
    asm volatile("ldmatrix.sync.aligned.m8n8.x4.shared.b16 {%0,%1,%2,%3}, [%4];"
                 : "=r"(r[0]), "=r"(r[1]), "=r"(r[2]), "=r"(r[3]) : "r"(addr));
}
__device__ __forceinline__ void ldsm_x2(uint32_t* r, uint32_t addr) {
    asm volatile("ldmatrix.sync.aligned.m8n8.x2.shared.b16 {%0,%1}, [%2];"
                 : "=r"(r[0]), "=r"(r[1]) : "r"(addr));
}
__device__ __forceinline__ void mma16816(float* c, const uint32_t* a,
                                         const uint32_t* b) {
    asm volatile("mma.sync.aligned.m16n8k16.row.col.f32.f16.f16.f32 "
                 "{%0,%1,%2,%3}, {%4,%5,%6,%7}, {%8,%9}, {%0,%1,%2,%3};"
                 : "+f"(c[0]), "+f"(c[1]), "+f"(c[2]), "+f"(c[3])
                 : "r"(a[0]), "r"(a[1]), "r"(a[2]), "r"(a[3]),
                   "r"(b[0]), "r"(b[1]));
}

// ---------------------------------------------------------------------------
__device__ __forceinline__ const float* map_src_row(
    int r, const float* __restrict__ E,
    const int* __restrict__ idxp, const int* __restrict__ idxr,
    const int* __restrict__ negp, const int* __restrict__ negr)
{
    if (r < Q_ROWS) {
        int t, local, S;
        if (r < 3600)      { t = 0; local = r;        S = 100; }
        else if (r < 7200) { t = 1; local = r - 3600; S = 100; }
        else if (r < 7920) { t = 2; local = r - 7200; S = 20;  }
        else               { t = 3; local = r - 7920; S = 20;  }
        int perxy = 6 * S;
        int xy  = local / perxy;
        int rem = local - xy * perxy;
        int node = (t < 2) ? idxp[t * 600 + rem] : idxr[(t - 2) * 120 + rem];
        int x = xy / LL, y = xy - x * LL;
        return E + ((size_t)(((t * VV + x) * LL + y) * N_NODES + node)) * D;
    } else {
        int rr = r - Q_ROWS;
        int t, local, K;
        if (rr < 900)       { t = 0; local = rr;        K = 50; }
        else if (rr < 1800) { t = 1; local = rr - 900;  K = 50; }
        else if (rr < 1980) { t = 2; local = rr - 1800; K = 10; }
        else                { t = 3; local = rr - 1980; K = 10; }
        int perO = 6 * K;
        int o   = local / perO;
        int vlk = local - o * perO;
        int vl  = vlk / K;
        int k   = vlk - vl * K;
        int off = (vl * 3 + o) * K + k;
        int node = (t < 2) ? negp[t * 900 + off] : negr[(t - 2) * 180 + off];
        int ot = o + (o >= t ? 1 : 0);
        int v = vl / LL, l = vl - v * LL;
        return E + ((size_t)(((ot * VV + v) * LL + l) * N_NODES + node)) * D;
    }
}

// ---------------------------------------------------------------------------
// Projection: 1024 threads, 32 warps (4 my x 8 cx), HMMA MLP, fp16 out.
#define SMA   0
#define SMW   67584
#define CTRL  202752
#define SM_BYTES (CTRL + 3072 + 4096)

#define APITCH 264

__global__ void __launch_bounds__(1024, 1)
proj_mma_kernel(const float* __restrict__ E,
                const float* __restrict__ W1, const float* __restrict__ b1,
                const float* __restrict__ W2, const float* __restrict__ b2,
                const int* __restrict__ idxp, const int* __restrict__ idxr,
                const int* __restrict__ negp, const int* __restrict__ negr)
{
    extern __shared__ char sm[];
    const uint32_t smb = smem_u32(sm);

    float* smb1 = (float*)(sm + CTRL);
    float* smb2 = (float*)(sm + CTRL + 1024);
    const float** srcp = (const float**)(sm + CTRL + 2048);
    float* ssbuf = (float*)(sm + CTRL + 3072);   // [128][8]

    const int tid = threadIdx.x;
    const int l   = tid & 31;
    const int w   = tid >> 5;
    const int my  = w >> 3;          // 0..3
    const int cx  = w & 7;           // 0..7
    const int r0  = blockIdx.x * ROWS_PB;

    if (blockIdx.x == 0) {
        for (int i = tid; i < N_ANCHORS; i += 1024) { g_pos[i] = 0.f; g_neg[i] = 0.f; }
        if (tid == 0) g_ctr = 0u;
    }

    if (tid < 64)        ((float4*)smb1)[tid]      = ((const float4*)b1)[tid];
    else if (tid < 128)  ((float4*)smb2)[tid - 64] = ((const float4*)b2)[tid - 64];
    if (tid < ROWS_PB) {
        int r = r0 + tid;
        srcp[tid] = (r < TOTAL_ROWS)
                  ? map_src_row(r, E, idxp, idxr, negp, negr)
                  : (const float*)0;
    }

    // W1 fp32 -> fp16 smem tile
    for (int i = tid; i < 16384; i += 1024) {
        int n = i >> 6, q = i & 63;
        float4 v = ((const float4*)W1)[i];
        __half2 p0 = __floats2half2_rn(v.x, v.y);
        __half2 p1 = __floats2half2_rn(v.z, v.w);
        uint2 pk = make_uint2(*reinterpret_cast<unsigned int*>(&p0),
                              *reinterpret_cast<unsigned int*>(&p1));
        *(uint2*)(sm + SMW + (n * APITCH + q * 4) * 2) = pk;
    }
    __syncthreads();

    // gather X -> fp16 A tile
    for (int i = tid; i < ROWS_PB * 64; i += 1024) {
        int m = i >> 6, q = i & 63;
        const float* s = srcp[m];
        float4 v = make_float4(0.f, 0.f, 0.f, 0.f);
        if (s) v = ((const float4*)s)[q];
        __half2 p0 = __floats2half2_rn(v.x, v.y);
        __half2 p1 = __floats2half2_rn(v.z, v.w);
        uint2 pk = make_uint2(*reinterpret_cast<unsigned int*>(&p0),
                              *reinterpret_cast<unsigned int*>(&p1));
        *(uint2*)(sm + SMA + (m * APITCH + q * 4) * 2) = pk;
    }
    __syncthreads();

    const uint32_t a_base = smb + SMA +
        ((my * 32 + ((l >> 3) & 1) * 8 + (l & 7)) * APITCH + (l >> 4) * 8) * 2;
    const uint32_t b_base = smb + SMW +
        ((cx * 32 + (l & 7)) * APITCH + ((l >> 3) & 1) * 8) * 2;

    float c[2][4][4];

    // layer 1
    #pragma unroll
    for (int mt = 0; mt < 2; mt++)
        #pragma unroll
        for (int nt = 0; nt < 4; nt++)
            #pragma unroll
            for (int j = 0; j < 4; j++) c[mt][nt][j] = 0.f;

    #pragma unroll 4
    for (int kk = 0; kk < 16; kk++) {
        uint32_t a[8];
        ldsm_x4(a,     a_base + kk * 32);
        ldsm_x4(a + 4, a_base + kk * 32 + 16 * APITCH * 2);
        #pragma unroll
        for (int nt = 0; nt < 4; nt++) {
            uint32_t b[2];
            ldsm_x2(b, b_base + kk * 32 + nt * 8 * APITCH * 2);
            mma16816(c[0][nt], a,     b);
            mma16816(c[1][nt], a + 4, b);
        }
    }
    __syncthreads();

    const int g  = l >> 2;
    const int q2 = (l & 3) * 2;
    #pragma unroll
    for (int mt = 0; mt < 2; mt++) {
        #pragma unroll
        for (int nt = 0; nt < 4; nt++) {
            int col = cx * 32 + nt * 8 + q2;
            float bx = smb1[col], by = smb1[col + 1];
            int rlo = my * 32 + mt * 16 + g;
            __half2 lo = __floats2half2_rn(fmaxf(c[mt][nt][0] + bx, 0.f),
                                           fmaxf(c[mt][nt][1] + by, 0.f));
            __half2 hi = __floats2half2_rn(fmaxf(c[mt][nt][2] + bx, 0.f),
                                           fmaxf(c[mt][nt][3] + by, 0.f));
            *(unsigned int*)(sm + SMA + (rlo * APITCH + col) * 2) =
                *reinterpret_cast<unsigned int*>(&lo);
            *(unsigned int*)(sm + SMA + ((rlo + 8) * APITCH + col) * 2) =
                *reinterpret_cast<unsigned int*>(&hi);
        }
    }
    // W2 fp32 -> fp16 smem tile
    for (int i = tid; i < 16384; i += 1024) {
        int n = i >> 6, q = i & 63;
        float4 v = ((const float4*)W2)[i];
        __half2 p0 = __floats2half2_rn(v.x, v.y);
        __half2 p1 = __floats2half2_rn(v.z, v.w);
        uint2 pk = make_uint2(*reinterpret_cast<unsigned int*>(&p0),
                              *reinterpret_cast<unsigned int*>(&p1));
        *(uint2*)(sm + SMW + (n * APITCH + q * 4) * 2) = pk;
    }
    __syncthreads();

    // layer 2
    #pragma unroll
    for (int mt = 0; mt < 2; mt++)
        #pragma unroll
        for (int nt = 0; nt < 4; nt++)
            #pragma unroll
            for (int j = 0; j < 4; j++) c[mt][nt][j] = 0.f;

    #pragma unroll 4
    for (int kk = 0; kk < 16; kk++) {
        uint32_t a[8];
        ldsm_x4(a,     a_base + kk * 32);
        ldsm_x4(a + 4, a_base + kk * 32 + 16 * APITCH * 2);
        #pragma unroll
        for (int nt = 0; nt < 4; nt++) {
            uint32_t b[2];
            ldsm_x2(b, b_base + kk * 32 + nt * 8 * APITCH * 2);
            mma16816(c[0][nt], a,     b);
            mma16816(c[1][nt], a + 4, b);
        }
    }

    // epilogue: bias, row L2-norm, fp16 store
    float ss[4] = {0.f, 0.f, 0.f, 0.f};
    #pragma unroll
    for (int mt = 0; mt < 2; mt++) {
        #pragma unroll
        for (int nt = 0; nt < 4; nt++) {
            int col = cx * 32 + nt * 8 + q2;
            float bx = smb2[col], by = smb2[col + 1];
            float z0 = c[mt][nt][0] + bx, z1 = c[mt][nt][1] + by;
            float z2 = c[mt][nt][2] + bx, z3 = c[mt][nt][3] + by;
            ss[mt * 2]     += z0 * z0 + z1 * z1;
            ss[mt * 2 + 1] += z2 * z2 + z3 * z3;
        }
    }
    #pragma unroll
    for (int j = 0; j < 4; j++) {
        ss[j] += __shfl_xor_sync(0xffffffffu, ss[j], 1);
        ss[j] += __shfl_xor_sync(0xffffffffu, ss[j], 2);
    }
    if ((l & 3) == 0) {
        #pragma unroll
        for (int j = 0; j < 4; j++) {
            int row = my * 32 + (j >> 1) * 16 + (j & 1) * 8 + g;
            ssbuf[row * 8 + cx] = ss[j];
        }
    }
    __syncthreads();

    float inv[4];
    #pragma unroll
    for (int j = 0; j < 4; j++) {
        int row = my * 32 + (j >> 1) * 16 + (j & 1) * 8 + g;
        float t = 0.f;
        #pragma unroll
        for (int c8 = 0; c8 < 8; c8++) t += ssbuf[row * 8 + c8];
        inv[j] = 1.0f / fmaxf(sqrtf(t), 1e-12f);
    }

    #pragma unroll
    for (int mt = 0; mt < 2; mt++) {
        #pragma unroll
        for (int nt = 0; nt < 4; nt++) {
            int col = cx * 32 + nt * 8 + q2;
            float bx = smb2[col], by = smb2[col + 1];
            int rlo = r0 + my * 32 + mt * 16 + g;
            int rhi = rlo + 8;
            int ci = (col >> 1);
            if (rlo < TOTAL_ROWS) {
                __half2 h = __floats2half2_rn((c[mt][nt][0] + bx) * inv[mt * 2],
                                              (c[mt][nt][1] + by) * inv[mt * 2]);
                g_projh[(size_t)rlo * 128 + ci] = *reinterpret_cast<unsigned int*>(&h);
            }
            if (rhi < TOTAL_ROWS) {
                __half2 h = __floats2half2_rn((c[mt][nt][2] + bx) * inv[mt * 2 + 1],
                                              (c[mt][nt][3] + by) * inv[mt * 2 + 1]);
                g_projh[(size_t)rhi * 128 + ci] = *reinterpret_cast<unsigned int*>(&h);
            }
        }
    }
}

// ---------------------------------------------------------------------------
// Loss: 84 blocks x 512 threads (16 warps: 2 my x 8 cx). M64 x N256 x K256.
// Smem tinfo[] table kills per-sim integer divisions. Fused finalize.
#define LSMA 0
#define LSMB 34816
#define LTRG 169984
#define LSM_BYTES (LTRG + 2048 + 128)

__global__ void __launch_bounds__(512, 1)
loss_mma_kernel(float* __restrict__ out)
{
    extern __shared__ char sm[];
    const uint32_t smb = smem_u32(sm);
    int* targ  = (int*)(sm + LTRG);
    int* tinfo = (int*)(sm + LTRG + 1024);

    const int tid = threadIdx.x;
    const int l   = tid & 31;
    const int w   = tid >> 5;
    const int my  = w >> 3;          // 0..1
    const int cx  = w & 7;           // 0..7
    const int b   = blockIdx.x;

    int S, K, vl, chunk, mtile, qbase, pbase, aid0;
    if (b < 72) {
        int t = b / 36, rem = b % 36;
        vl = rem / 6;
        int r2 = rem % 6;
        mtile = r2 / 3; chunk = r2 % 3;
        S = 100; K = 50;
        qbase = t * 3600; pbase = t * 900;
        aid0  = t * 600 + vl * 100;
    } else {
        int bs = b - 72;
        int t2 = bs / 6;
        vl = bs % 6; chunk = 0; mtile = 0;
        S = 20; K = 10;
        qbase = 7200 + t2 * 720; pbase = 1800 + t2 * 180;
        aid0  = 1200 + t2 * 120 + vl * 20;
    }
    const int NTARG = 6 * S + 3 * K;
    const int diag_base = qbase + vl * 7 * S;
    const int mrow0 = mtile * 64;

    // target row table + classification table (one IDIV per column, not per sim)
    if (tid < 256) {
        int n = chunk * 256 + tid;
        int row = 0, info = 0;
        if (n < 6 * S) {
            int xy = n / S, ts = n - xy * S;
            row  = qbase + (xy * 6 + vl) * S + ts;
            info = ts | ((xy == vl) ? 0x10000 : 0) | 0x40000;
        } else if (n < NTARG) {
            int cc = n - 6 * S;
            int o = cc / K, k = cc - o * K;
            row  = Q_ROWS + pbase + (o * 6 + vl) * K + k;
            info = 0x20000 | 0x40000;
        }
        targ[tid]  = row;
        tinfo[tid] = info;
    }
    __syncthreads();

    // A (64 anchors) and B (256 targets) fp16 tiles
    for (int i = tid; i < 64 * 32; i += 512) {
        int r = i >> 5, q = i & 31;
        int gr = mrow0 + r;
        int arow = diag_base + (gr < S ? gr : 0);
        *(float4*)(sm + LSMA + (r * APITCH + q * 8) * 2) =
            ((const float4*)g_projh)[(size_t)arow * 32 + q];
    }
    for (int i = tid; i < 256 * 32; i += 512) {
        int r = i >> 5, q = i & 31;
        *(float4*)(sm + LSMB + (r * APITCH + q * 8) * 2) =
            ((const float4*)g_projh)[(size_t)targ[r] * 32 + q];
    }
    __syncthreads();

    const uint32_t a_base = smb + LSMA +
        ((my * 32 + ((l >> 3) & 1) * 8 + (l & 7)) * APITCH + (l >> 4) * 8) * 2;
    const uint32_t b_base = smb + LSMB +
        ((cx * 32 + (l & 7)) * APITCH + ((l >> 3) & 1) * 8) * 2;

    float c[2][4][4];
    #pragma unroll
    for (int mt = 0; mt < 2; mt++)
        #pragma unroll
        for (int nt = 0; nt < 4; nt++)
            #pragma unroll
            for (int j = 0; j < 4; j++) c[mt][nt][j] = 0.f;

    #pragma unroll 4
    for (int kk = 0; kk < 16; kk++) {
        uint32_t a[8];
        ldsm_x4(a,     a_base + kk * 32);
        ldsm_x4(a + 4, a_base + kk * 32 + 16 * APITCH * 2);
        #pragma unroll
        for (int nt = 0; nt < 4; nt++) {
            uint32_t bb[2];
            ldsm_x2(bb, b_base + kk * 32 + nt * 8 * APITCH * 2);
            mma16816(c[0][nt], a,     bb);
            mma16816(c[1][nt], a + 4, bb);
        }
    }

    const int g  = l >> 2;
    const int q2 = (l & 3) * 2;
    float pacc[4] = {0.f, 0.f, 0.f, 0.f};
    float nacc[4] = {0.f, 0.f, 0.f, 0.f};

    int rowg[4];
    #pragma unroll
    for (int s = 0; s < 4; s++)
        rowg[s] = mrow0 + my * 32 + (s >> 1) * 16 + (s & 1) * 8 + g;

    #pragma unroll
    for (int nt = 0; nt < 4; nt++) {
        #pragma unroll
        for (int jl = 0; jl < 2; jl++) {
            int info = tinfo[cx * 32 + nt * 8 + q2 + jl];
            if (info & 0x40000) {
                int ts = info & 0xFFFF;
                #pragma unroll
                for (int mt = 0; mt < 2; mt++) {
                    #pragma unroll
                    for (int jh = 0; jh < 2; jh++) {
                        int s = mt * 2 + jh;
                        if (rowg[s] < S) {
                            float e = __expf(2.0f * c[mt][nt][jh * 2 + jl]);
                            if (info & 0x20000)        nacc[s] += e;          // cross
                            else if (info & 0x10000) { if (ts != rowg[s]) nacc[s] += e; }
                            else if (ts == rowg[s])    pacc[s] += e;          // positive
                        }
                    }
                }
            }
        }
    }

    #pragma unroll
    for (int s = 0; s < 4; s++) {
        pacc[s] += __shfl_xor_sync(0xffffffffu, pacc[s], 1);
        pacc[s] += __shfl_xor_sync(0xffffffffu, pacc[s], 2);
        nacc[s] += __shfl_xor_sync(0xffffffffu, nacc[s], 1);
        nacc[s] += __shfl_xor_sync(0xffffffffu, nacc[s], 2);
    }
    if ((l & 3) == 0) {
        #pragma unroll
        for (int s = 0; s < 4; s++) {
            if (rowg[s] < S) {
                if (pacc[s] != 0.f) atomicAdd(&g_pos[aid0 + rowg[s]], pacc[s]);
                if (nacc[s] != 0.f) atomicAdd(&g_neg[aid0 + rowg[s]], nacc[s]);
            }
        }
    }

    // ---- fused finalize ----
    __shared__ unsigned int is_last;
    __threadfence();
    __syncthreads();
    if (tid == 0)
        is_last = (atomicAdd(&g_ctr, 1u) == (unsigned)(gridDim.x - 1));
    __syncthreads();
    if (is_last) {
        float loc = 0.f;
        for (int i = tid; i < N_ANCHORS; i += 512) {
            float p = g_pos[i], n = g_neg[i];
            loc += -logf(p / (p + n));
        }
        loc += __shfl_xor_sync(0xffffffffu, loc, 16);
        loc += __shfl_xor_sync(0xffffffffu, loc, 8);
        loc += __shfl_xor_sync(0xffffffffu, loc, 4);
        loc += __shfl_xor_sync(0xffffffffu, loc, 2);
        loc += __shfl_xor_sync(0xffffffffu, loc, 1);
        float* red = (float*)(sm + LTRG + 2048);
        if (l == 0) red[w] = loc;
        __syncthreads();
        if (w == 0) {
            float s = (l < 16) ? red[l] : 0.f;
            s += __shfl_xor_sync(0xffffffffu, s, 8);
            s += __shfl_xor_sync(0xffffffffu, s, 4);
            s += __shfl_xor_sync(0xffffffffu, s, 2);
            s += __shfl_xor_sync(0xffffffffu, s, 1);
            if (l == 0) out[0] = s * (1.0f / 1440.0f);
        }
    }
}

// ---------------------------------------------------------------------------
extern "C" void kernel_launch(void* const* d_in, const int* in_sizes, int n_in,
                              void* d_out, int out_size)
{
    const float* E    = (const float*)d_in[0];
    const float* W1   = (const float*)d_in[1];
    const float* b1   = (const float*)d_in[2];
    const float* W2   = (const float*)d_in[3];
    const float* b2   = (const float*)d_in[4];
    const int*   idxp = (const int*)d_in[5];
    const int*   idxr = (const int*)d_in[6];
    const int*   negp = (const int*)d_in[7];
    const int*   negr = (const int*)d_in[8];
    float* out = (float*)d_out;
    (void)in_sizes; (void)n_in; (void)out_size;

    cudaFuncSetAttribute(proj_mma_kernel,
                         cudaFuncAttributeMaxDynamicSharedMemorySize, SM_BYTES);
    cudaFuncSetAttribute(loss_mma_kernel,
                         cudaFuncAttributeMaxDynamicSharedMemorySize, LSM_BYTES);

    proj_mma_kernel<<<PROJ_BLOCKS, 1024, SM_BYTES>>>(E, W1, b1, W2, b2,
                                                     idxp, idxr, negp, negr);
    loss_mma_kernel<<<84, 512, LSM_BYTES>>>(out);
}